// round 1
// baseline (speedup 1.0000x reference)
#include <cuda_runtime.h>
#include <cstdint>
#include <cstddef>

#define MAXN 100000

// Scratch (device globals: allocation-free, rewritten every launch)
__device__ float g_g[MAXN * 128];      // g = dinv * (h @ W), gather source
__device__ float g_acc_a[MAXN * 128];  // ping-pong accumulators
__device__ float g_acc_b[MAXN * 128];
__device__ float g_dinv[MAXN];
__device__ int   g_deg[MAXN];

// ---------------------------------------------------------------------------
// Degree / dinv
// ---------------------------------------------------------------------------
__global__ void k_zero_deg(int n) {
    int i = blockIdx.x * blockDim.x + threadIdx.x;
    if (i < n) g_deg[i] = 0;
}

__global__ void k_count(const int* __restrict__ col, int E) {
    int i = blockIdx.x * blockDim.x + threadIdx.x;
    if (i < E) atomicAdd(&g_deg[col[i]], 1);
}

__global__ void k_dinv(int n) {
    int i = blockIdx.x * blockDim.x + threadIdx.x;
    if (i < n) g_dinv[i] = rsqrtf((float)g_deg[i] + 1.0f);  // +1 self loop
}

// ---------------------------------------------------------------------------
// Fused GEMM: 64-node tile per block, 128 threads.
// MODE 0: in = x raw;             epilogue: g = acc = dinv * (h@W)
// MODE 1: prologue relu(dinv*in + bprev); epilogue: g = acc = dinv * dot
// MODE 2: prologue relu(dinv*in + bprev); epilogue: out = dot + bout
// ---------------------------------------------------------------------------
template <int FI, int FO, int MODE>
__global__ __launch_bounds__(128)
void k_gemm(const float* __restrict__ in, const float* __restrict__ W,
            const float* __restrict__ bprev, const float* __restrict__ bout,
            float* __restrict__ g, float* __restrict__ acc,
            float* __restrict__ out, int n)
{
    extern __shared__ float smem[];
    float* shH = smem;                    // 64 x (FI+1)  (pad 1 -> low conflicts)
    float* shW = smem + 64 * (FI + 1);    // FI x FO

    const int tid   = threadIdx.x;
    const int node0 = blockIdx.x * 64;

    // Stage W
    #pragma unroll 4
    for (int i = tid; i < FI * FO / 4; i += 128)
        ((float4*)shW)[i] = ((const float4*)W)[i];

    // Stage h tile with fused prologue
    for (int i = tid; i < 64 * FI / 4; i += 128) {
        int node = (i * 4) / FI;
        int f    = (i * 4) - node * FI;
        int gn   = node0 + node;
        float4 v = make_float4(0.f, 0.f, 0.f, 0.f);
        float dv = 0.f;
        if (gn < n) {
            v = *(const float4*)(in + (size_t)gn * FI + f);
            if (MODE) dv = g_dinv[gn];
        }
        float t0 = v.x, t1 = v.y, t2 = v.z, t3 = v.w;
        if (MODE) {
            t0 = fmaxf(fmaf(t0, dv, bprev[f + 0]), 0.f);
            t1 = fmaxf(fmaf(t1, dv, bprev[f + 1]), 0.f);
            t2 = fmaxf(fmaf(t2, dv, bprev[f + 2]), 0.f);
            t3 = fmaxf(fmaf(t3, dv, bprev[f + 3]), 0.f);
        }
        float* hrow = shH + node * (FI + 1) + f;
        hrow[0] = t0; hrow[1] = t1; hrow[2] = t2; hrow[3] = t3;
    }
    __syncthreads();

    // Register-tiled compute: 4 nodes x CN outputs per thread
    constexpr int CN = FO / 8;
    const int tx = tid & 7;    // 8 groups along fo
    const int ty = tid >> 3;   // 16 groups along nodes
    const int nb = ty * 4;
    const int fb = tx * CN;

    float accr[4][CN];
    #pragma unroll
    for (int r = 0; r < 4; r++)
        #pragma unroll
        for (int c = 0; c < CN; c++) accr[r][c] = 0.f;

    #pragma unroll 4
    for (int k = 0; k < FI; k++) {
        float a0 = shH[(nb + 0) * (FI + 1) + k];
        float a1 = shH[(nb + 1) * (FI + 1) + k];
        float a2 = shH[(nb + 2) * (FI + 1) + k];
        float a3 = shH[(nb + 3) * (FI + 1) + k];
        #pragma unroll
        for (int c = 0; c < CN; c++) {
            float w = shW[k * FO + fb + c];
            accr[0][c] = fmaf(a0, w, accr[0][c]);
            accr[1][c] = fmaf(a1, w, accr[1][c]);
            accr[2][c] = fmaf(a2, w, accr[2][c]);
            accr[3][c] = fmaf(a3, w, accr[3][c]);
        }
    }

    #pragma unroll
    for (int r = 0; r < 4; r++) {
        int gn = node0 + nb + r;
        if (gn >= n) continue;
        if (MODE < 2) {
            float dv = g_dinv[gn];
            #pragma unroll
            for (int c = 0; c < CN; c++) {
                float vv = accr[r][c] * dv;
                g[(size_t)gn * FO + fb + c]   = vv;  // gather source
                acc[(size_t)gn * FO + fb + c] = vv;  // self-loop init
            }
        } else {
            #pragma unroll
            for (int c = 0; c < CN; c++)
                out[(size_t)gn * FO + fb + c] = accr[r][c] + bout[fb + c];
        }
    }
}

// ---------------------------------------------------------------------------
// Edge scatter: thread = (edge, 4-feature chunk). Consecutive lanes cover one
// edge's contiguous feature row -> coalesced gathers & vector reductions.
// ---------------------------------------------------------------------------
template <int FO>
__global__ __launch_bounds__(256)
void k_scatter(const float* __restrict__ g, float* __restrict__ acc,
               const int* __restrict__ row, const int* __restrict__ col,
               long long total, int /*E*/)
{
    constexpr int CH = FO / 4;
    long long idx = (long long)blockIdx.x * 256 + threadIdx.x;
    if (idx >= total) return;
    int e = (int)(idx / CH);
    int c = (int)(idx - (long long)e * CH);
    int r  = __ldg(row + e);
    int co = __ldg(col + e);
    float4 v = __ldg((const float4*)(g + (size_t)r * FO) + c);
    float* dst = acc + (size_t)co * FO + (size_t)c * 4;
    asm volatile("red.global.add.v4.f32 [%0], {%1,%2,%3,%4};"
                 :: "l"(dst), "f"(v.x), "f"(v.y), "f"(v.z), "f"(v.w)
                 : "memory");
}

// ---------------------------------------------------------------------------
// Host launcher
// ---------------------------------------------------------------------------
static inline int smem_bytes(int fi, int fo) { return (64 * (fi + 1) + fi * fo) * 4; }

template <int FI, int FO, int MODE>
static void launch_gemm(const float* in, const float* W, const float* bprev,
                        const float* bout, float* g, float* acc, float* out, int n)
{
    int sm = smem_bytes(FI, FO);
    cudaFuncSetAttribute((const void*)k_gemm<FI, FO, MODE>,
                         cudaFuncAttributeMaxDynamicSharedMemorySize, sm);
    k_gemm<FI, FO, MODE><<<(n + 63) / 64, 128, sm>>>(in, W, bprev, bout, g, acc, out, n);
}

template <int FO>
static void launch_scatter(const float* g, float* acc, const int* row,
                           const int* col, int E)
{
    long long total = (long long)E * (FO / 4);
    int blocks = (int)((total + 255) / 256);
    k_scatter<FO><<<blocks, 256>>>(g, acc, row, col, total, E);
}

extern "C" void kernel_launch(void* const* d_in, const int* in_sizes, int n_in,
                              void* d_out, int out_size)
{
    const float* x  = (const float*)d_in[0];
    const int*   ei = (const int*)d_in[1];
    const int n = in_sizes[0] / 128;
    const int E = in_sizes[1] / 2;
    const int* row = ei;        // source j
    const int* col = ei + E;    // target i

    const float* W1 = (const float*)d_in[3];  const float* b1 = (const float*)d_in[4];
    const float* W2 = (const float*)d_in[5];  const float* b2 = (const float*)d_in[6];
    const float* W3 = (const float*)d_in[7];  const float* b3 = (const float*)d_in[8];
    const float* W4 = (const float*)d_in[9];  const float* b4 = (const float*)d_in[10];
    const float* W5 = (const float*)d_in[11]; const float* b5 = (const float*)d_in[12];
    const float* W6 = (const float*)d_in[13]; const float* b6 = (const float*)d_in[14];
    const float* Wf = (const float*)d_in[15]; const float* bf = (const float*)d_in[16];

    float *gptr, *accA, *accB;
    cudaGetSymbolAddress((void**)&gptr, g_g);
    cudaGetSymbolAddress((void**)&accA, g_acc_a);
    cudaGetSymbolAddress((void**)&accB, g_acc_b);
    float* dout = (float*)d_out;

    // Degree + dinv (recomputed every replay: deterministic, capture-safe)
    k_zero_deg<<<(n + 255) / 256, 256>>>(n);
    k_count<<<(E + 255) / 256, 256>>>(col, E);
    k_dinv<<<(n + 255) / 256, 256>>>(n);

    // Layer 1: x -> (g, accA), fo=64
    launch_gemm<128, 64, 0>(x, W1, nullptr, nullptr, gptr, accA, nullptr, n);
    launch_scatter<64>(gptr, accA, row, col, E);

    // Layer 2: accA -> (g, accB), fo=32
    launch_gemm<64, 32, 1>(accA, W2, b1, nullptr, gptr, accB, nullptr, n);
    launch_scatter<32>(gptr, accB, row, col, E);

    // Layer 3: accB -> (g, accA), fo=16
    launch_gemm<32, 16, 1>(accB, W3, b2, nullptr, gptr, accA, nullptr, n);
    launch_scatter<16>(gptr, accA, row, col, E);

    // Layer 4: accA -> (g, accB), fo=32
    launch_gemm<16, 32, 1>(accA, W4, b3, nullptr, gptr, accB, nullptr, n);
    launch_scatter<32>(gptr, accB, row, col, E);

    // Layer 5: accB -> (g, accA), fo=64
    launch_gemm<32, 64, 1>(accB, W5, b4, nullptr, gptr, accA, nullptr, n);
    launch_scatter<64>(gptr, accA, row, col, E);

    // Layer 6: accA -> (g, accB), fo=128
    launch_gemm<64, 128, 1>(accA, W6, b5, nullptr, gptr, accB, nullptr, n);
    launch_scatter<128>(gptr, accB, row, col, E);

    // Final linear: relu(dinv*accB + b6) @ Wf + bf -> out
    launch_gemm<128, 128, 2>(accB, Wf, b6, bf, nullptr, nullptr, dout, n);
}

// round 2
// speedup vs baseline: 1.6911x; 1.6911x over previous
#include <cuda_runtime.h>
#include <cstdint>
#include <cstddef>

#define MAXN 100000
#define MAXE 3200000

// Scratch (device globals: allocation-free, rewritten every replay)
__device__ float g_g[MAXN * 128];      // g = dinv * (h @ W), gather source
__device__ float g_acc[MAXN * 128];    // aggregation result
__device__ float g_dinv[MAXN];
__device__ int   g_deg[MAXN];
__device__ int   g_offs[MAXN + 1];
__device__ int   g_cur[MAXN];
__device__ int   g_csr[MAXE];          // edge sources grouped by destination
__device__ int   g_part[128];

// ---------------------------------------------------------------------------
// Degree / dinv / CSR build
// ---------------------------------------------------------------------------
__global__ void k_zero_deg(int n) {
    int i = blockIdx.x * blockDim.x + threadIdx.x;
    if (i < n) g_deg[i] = 0;
}

__global__ void k_count(const int* __restrict__ col, int E) {
    int i = blockIdx.x * blockDim.x + threadIdx.x;
    if (i < E) atomicAdd(&g_deg[col[i]], 1);
}

__global__ void k_dinv(int n) {
    int i = blockIdx.x * blockDim.x + threadIdx.x;
    if (i < n) g_dinv[i] = rsqrtf((float)g_deg[i] + 1.0f);  // +1 self loop
}

// Pass 1: per-block exclusive scan of deg -> offs, block totals -> part
__global__ __launch_bounds__(1024) void k_scan1(int n) {
    __shared__ int sh[1024];
    int i = blockIdx.x * 1024 + threadIdx.x;
    int v = (i < n) ? g_deg[i] : 0;
    sh[threadIdx.x] = v;
    __syncthreads();
    for (int d = 1; d < 1024; d <<= 1) {
        int t = (threadIdx.x >= d) ? sh[threadIdx.x - d] : 0;
        __syncthreads();
        sh[threadIdx.x] += t;
        __syncthreads();
    }
    if (i < n) g_offs[i] = sh[threadIdx.x] - v;  // exclusive
    if (threadIdx.x == 1023) g_part[blockIdx.x] = sh[1023];
}

// Pass 2: single-block exclusive scan of partials (nb <= 128)
__global__ __launch_bounds__(128) void k_scan2(int nb) {
    __shared__ int sh[128];
    int v = (threadIdx.x < nb) ? g_part[threadIdx.x] : 0;
    sh[threadIdx.x] = v;
    __syncthreads();
    for (int d = 1; d < 128; d <<= 1) {
        int t = (threadIdx.x >= d) ? sh[threadIdx.x - d] : 0;
        __syncthreads();
        sh[threadIdx.x] += t;
        __syncthreads();
    }
    if (threadIdx.x < nb) g_part[threadIdx.x] = sh[threadIdx.x] - v;  // exclusive
}

// Pass 3: add block offsets, zero cursors, set sentinel
__global__ void k_scan3(int n, int E) {
    int i = blockIdx.x * blockDim.x + threadIdx.x;
    if (i < n) {
        g_offs[i] += g_part[i >> 10];
        g_cur[i] = 0;
    }
    if (i == 0) g_offs[n] = E;
}

__global__ void k_fill(const int* __restrict__ row, const int* __restrict__ col, int E) {
    int e = blockIdx.x * blockDim.x + threadIdx.x;
    if (e < E) {
        int c = col[e];
        int p = g_offs[c] + atomicAdd(&g_cur[c], 1);
        g_csr[p] = row[e];
    }
}

// ---------------------------------------------------------------------------
// Fused GEMM: 64-node tile per block, 128 threads.
// MODE 0: in = x raw;                     epilogue: g = dinv * (h@W)
// MODE 1: prologue relu(dinv*in + bprev); epilogue: g = dinv * dot
// MODE 2: prologue relu(dinv*in + bprev); epilogue: out = dot + bout
// ---------------------------------------------------------------------------
template <int FI, int FO, int MODE>
__global__ __launch_bounds__(128)
void k_gemm(const float* __restrict__ in, const float* __restrict__ W,
            const float* __restrict__ bprev, const float* __restrict__ bout,
            float* __restrict__ g, float* __restrict__ out, int n)
{
    extern __shared__ float smem[];
    float* shH = smem;                    // 64 x (FI+1)
    float* shW = smem + 64 * (FI + 1);    // FI x FO

    const int tid   = threadIdx.x;
    const int node0 = blockIdx.x * 64;

    #pragma unroll 4
    for (int i = tid; i < FI * FO / 4; i += 128)
        ((float4*)shW)[i] = ((const float4*)W)[i];

    for (int i = tid; i < 64 * FI / 4; i += 128) {
        int node = (i * 4) / FI;
        int f    = (i * 4) - node * FI;
        int gn   = node0 + node;
        float4 v = make_float4(0.f, 0.f, 0.f, 0.f);
        float dv = 0.f;
        if (gn < n) {
            v = *(const float4*)(in + (size_t)gn * FI + f);
            if (MODE) dv = g_dinv[gn];
        }
        float t0 = v.x, t1 = v.y, t2 = v.z, t3 = v.w;
        if (MODE) {
            t0 = fmaxf(fmaf(t0, dv, bprev[f + 0]), 0.f);
            t1 = fmaxf(fmaf(t1, dv, bprev[f + 1]), 0.f);
            t2 = fmaxf(fmaf(t2, dv, bprev[f + 2]), 0.f);
            t3 = fmaxf(fmaf(t3, dv, bprev[f + 3]), 0.f);
        }
        float* hrow = shH + node * (FI + 1) + f;
        hrow[0] = t0; hrow[1] = t1; hrow[2] = t2; hrow[3] = t3;
    }
    __syncthreads();

    constexpr int CN = FO / 8;
    const int tx = tid & 7;
    const int ty = tid >> 3;
    const int nb = ty * 4;
    const int fb = tx * CN;

    float accr[4][CN];
    #pragma unroll
    for (int r = 0; r < 4; r++)
        #pragma unroll
        for (int c = 0; c < CN; c++) accr[r][c] = 0.f;

    #pragma unroll 4
    for (int k = 0; k < FI; k++) {
        float a0 = shH[(nb + 0) * (FI + 1) + k];
        float a1 = shH[(nb + 1) * (FI + 1) + k];
        float a2 = shH[(nb + 2) * (FI + 1) + k];
        float a3 = shH[(nb + 3) * (FI + 1) + k];
        #pragma unroll
        for (int c = 0; c < CN; c++) {
            float w = shW[k * FO + fb + c];
            accr[0][c] = fmaf(a0, w, accr[0][c]);
            accr[1][c] = fmaf(a1, w, accr[1][c]);
            accr[2][c] = fmaf(a2, w, accr[2][c]);
            accr[3][c] = fmaf(a3, w, accr[3][c]);
        }
    }

    #pragma unroll
    for (int r = 0; r < 4; r++) {
        int gn = node0 + nb + r;
        if (gn >= n) continue;
        if (MODE < 2) {
            float dv = g_dinv[gn];
            #pragma unroll
            for (int c = 0; c < CN; c++)
                g[(size_t)gn * FO + fb + c] = accr[r][c] * dv;
        } else {
            #pragma unroll
            for (int c = 0; c < CN; c++)
                out[(size_t)gn * FO + fb + c] = accr[r][c] + bout[fb + c];
        }
    }
}

// ---------------------------------------------------------------------------
// CSR gather-reduce: one node per LPN lanes. acc[i] = g[i] + sum_{j in N(i)} g[j]
// ---------------------------------------------------------------------------
template <int FO>
__global__ __launch_bounds__(256)
void k_gather(const float* __restrict__ gsrc, float* __restrict__ acc, int n)
{
    constexpr int LPN = (FO < 32) ? FO : 32;   // lanes per node
    constexpr int NPW = 32 / LPN;              // nodes per warp
    constexpr int VEC = FO / LPN;              // floats per lane

    int warp = (blockIdx.x * 256 + threadIdx.x) >> 5;
    int lane = threadIdx.x & 31;
    int node = warp * NPW + lane / LPN;
    if (node >= n) return;
    int li  = lane % LPN;
    int beg = g_offs[node];
    int end = g_offs[node + 1];

    const float* self = gsrc + (size_t)node * FO + li * VEC;
    float a[VEC];
    if (VEC == 4) {
        float4 v = __ldg((const float4*)self);
        a[0] = v.x; a[1] = v.y; a[2] = v.z; a[3] = v.w;
    } else if (VEC == 2) {
        float2 v = __ldg((const float2*)self);
        a[0] = v.x; a[1] = v.y;
    } else {
        a[0] = __ldg(self);
    }

    int e = beg;
    for (; e + 3 < end; e += 4) {
        int s0 = __ldg(g_csr + e + 0);
        int s1 = __ldg(g_csr + e + 1);
        int s2 = __ldg(g_csr + e + 2);
        int s3 = __ldg(g_csr + e + 3);
        const float* p0 = gsrc + (size_t)s0 * FO + li * VEC;
        const float* p1 = gsrc + (size_t)s1 * FO + li * VEC;
        const float* p2 = gsrc + (size_t)s2 * FO + li * VEC;
        const float* p3 = gsrc + (size_t)s3 * FO + li * VEC;
        if (VEC == 4) {
            float4 v0 = __ldg((const float4*)p0);
            float4 v1 = __ldg((const float4*)p1);
            float4 v2 = __ldg((const float4*)p2);
            float4 v3 = __ldg((const float4*)p3);
            a[0] += (v0.x + v1.x) + (v2.x + v3.x);
            a[1] += (v0.y + v1.y) + (v2.y + v3.y);
            a[2] += (v0.z + v1.z) + (v2.z + v3.z);
            a[3] += (v0.w + v1.w) + (v2.w + v3.w);
        } else if (VEC == 2) {
            float2 v0 = __ldg((const float2*)p0);
            float2 v1 = __ldg((const float2*)p1);
            float2 v2 = __ldg((const float2*)p2);
            float2 v3 = __ldg((const float2*)p3);
            a[0] += (v0.x + v1.x) + (v2.x + v3.x);
            a[1] += (v0.y + v1.y) + (v2.y + v3.y);
        } else {
            a[0] += (__ldg(p0) + __ldg(p1)) + (__ldg(p2) + __ldg(p3));
        }
    }
    for (; e < end; e++) {
        int s = __ldg(g_csr + e);
        const float* p = gsrc + (size_t)s * FO + li * VEC;
        if (VEC == 4) {
            float4 v = __ldg((const float4*)p);
            a[0] += v.x; a[1] += v.y; a[2] += v.z; a[3] += v.w;
        } else if (VEC == 2) {
            float2 v = __ldg((const float2*)p);
            a[0] += v.x; a[1] += v.y;
        } else {
            a[0] += __ldg(p);
        }
    }

    float* dst = acc + (size_t)node * FO + li * VEC;
    if (VEC == 4)      *(float4*)dst = make_float4(a[0], a[1], a[2], a[3]);
    else if (VEC == 2) *(float2*)dst = make_float2(a[0], a[1]);
    else               *dst = a[0];
}

// ---------------------------------------------------------------------------
// Host launcher
// ---------------------------------------------------------------------------
static inline int smem_bytes(int fi, int fo) { return (64 * (fi + 1) + fi * fo) * 4; }

template <int FI, int FO, int MODE>
static void launch_gemm(const float* in, const float* W, const float* bprev,
                        const float* bout, float* g, float* out, int n)
{
    int sm = smem_bytes(FI, FO);
    cudaFuncSetAttribute((const void*)k_gemm<FI, FO, MODE>,
                         cudaFuncAttributeMaxDynamicSharedMemorySize, sm);
    k_gemm<FI, FO, MODE><<<(n + 63) / 64, 128, sm>>>(in, W, bprev, bout, g, out, n);
}

template <int FO>
static void launch_gather(const float* g, float* acc, int n)
{
    constexpr int NPW = (FO < 32) ? (32 / FO) : 1;
    int warps  = (n + NPW - 1) / NPW;
    int blocks = (warps + 7) / 8;
    k_gather<FO><<<blocks, 256>>>(g, acc, n);
}

extern "C" void kernel_launch(void* const* d_in, const int* in_sizes, int n_in,
                              void* d_out, int out_size)
{
    const float* x  = (const float*)d_in[0];
    const int*   ei = (const int*)d_in[1];
    const int n = in_sizes[0] / 128;
    const int E = in_sizes[1] / 2;
    const int* row = ei;        // source j
    const int* col = ei + E;    // target i

    const float* W1 = (const float*)d_in[3];  const float* b1 = (const float*)d_in[4];
    const float* W2 = (const float*)d_in[5];  const float* b2 = (const float*)d_in[6];
    const float* W3 = (const float*)d_in[7];  const float* b3 = (const float*)d_in[8];
    const float* W4 = (const float*)d_in[9];  const float* b4 = (const float*)d_in[10];
    const float* W5 = (const float*)d_in[11]; const float* b5 = (const float*)d_in[12];
    const float* W6 = (const float*)d_in[13]; const float* b6 = (const float*)d_in[14];
    const float* Wf = (const float*)d_in[15]; const float* bf = (const float*)d_in[16];

    float *gptr, *acc;
    cudaGetSymbolAddress((void**)&gptr, g_g);
    cudaGetSymbolAddress((void**)&acc, g_acc);
    float* dout = (float*)d_out;

    // Degree + dinv + CSR (recomputed every replay: deterministic, capture-safe)
    k_zero_deg<<<(n + 255) / 256, 256>>>(n);
    k_count<<<(E + 255) / 256, 256>>>(col, E);
    k_dinv<<<(n + 255) / 256, 256>>>(n);
    int nb = (n + 1023) / 1024;
    k_scan1<<<nb, 1024>>>(n);
    k_scan2<<<1, 128>>>(nb);
    k_scan3<<<(n + 255) / 256, 256>>>(n, E);
    k_fill<<<(E + 255) / 256, 256>>>(row, col, E);

    // Layer 1: x -> g, gather -> acc   (fo=64)
    launch_gemm<128, 64, 0>(x, W1, nullptr, nullptr, gptr, nullptr, n);
    launch_gather<64>(gptr, acc, n);

    // Layer 2 (fo=32)
    launch_gemm<64, 32, 1>(acc, W2, b1, nullptr, gptr, nullptr, n);
    launch_gather<32>(gptr, acc, n);

    // Layer 3 (fo=16)
    launch_gemm<32, 16, 1>(acc, W3, b2, nullptr, gptr, nullptr, n);
    launch_gather<16>(gptr, acc, n);

    // Layer 4 (fo=32)
    launch_gemm<16, 32, 1>(acc, W4, b3, nullptr, gptr, nullptr, n);
    launch_gather<32>(gptr, acc, n);

    // Layer 5 (fo=64)
    launch_gemm<32, 64, 1>(acc, W5, b4, nullptr, gptr, nullptr, n);
    launch_gather<64>(gptr, acc, n);

    // Layer 6 (fo=128)
    launch_gemm<64, 128, 1>(acc, W6, b5, nullptr, gptr, nullptr, n);
    launch_gather<128>(gptr, acc, n);

    // Final linear: relu(dinv*acc + b6) @ Wf + bf -> out
    launch_gemm<128, 128, 2>(acc, Wf, b6, bf, nullptr, dout, n);
}

// round 3
// speedup vs baseline: 2.0940x; 1.2382x over previous
#include <cuda_runtime.h>
#include <cuda_fp16.h>
#include <cstdint>
#include <cstddef>

#define MAXN 100000
#define MAXE 3200000

// Scratch (device globals: allocation-free, rewritten every replay)
__device__ __half g_gh[MAXN * 128];    // g = dinv * (h @ W) in fp16, gather source
__device__ float  g_acc[MAXN * 128];   // aggregation result (fp32)
__device__ float  g_dinv[MAXN];
__device__ int    g_deg[MAXN];
__device__ int    g_offs[MAXN + 1];
__device__ int    g_cur[MAXN];
__device__ int    g_csr[MAXE];         // edge sources grouped by destination
__device__ int    g_part[128];

// ---------------------------------------------------------------------------
// Degree / dinv / CSR build
// ---------------------------------------------------------------------------
__global__ void k_zero_deg(int n) {
    int i = blockIdx.x * blockDim.x + threadIdx.x;
    if (i < n) g_deg[i] = 0;
}

__global__ void k_count(const int* __restrict__ col, int E) {
    int i = blockIdx.x * blockDim.x + threadIdx.x;
    if (i < E) atomicAdd(&g_deg[col[i]], 1);
}

__global__ void k_dinv(int n) {
    int i = blockIdx.x * blockDim.x + threadIdx.x;
    if (i < n) g_dinv[i] = rsqrtf((float)g_deg[i] + 1.0f);  // +1 self loop
}

__global__ __launch_bounds__(1024) void k_scan1(int n) {
    __shared__ int sh[1024];
    int i = blockIdx.x * 1024 + threadIdx.x;
    int v = (i < n) ? g_deg[i] : 0;
    sh[threadIdx.x] = v;
    __syncthreads();
    for (int d = 1; d < 1024; d <<= 1) {
        int t = (threadIdx.x >= d) ? sh[threadIdx.x - d] : 0;
        __syncthreads();
        sh[threadIdx.x] += t;
        __syncthreads();
    }
    if (i < n) g_offs[i] = sh[threadIdx.x] - v;  // exclusive
    if (threadIdx.x == 1023) g_part[blockIdx.x] = sh[1023];
}

__global__ __launch_bounds__(128) void k_scan2(int nb) {
    __shared__ int sh[128];
    int v = (threadIdx.x < nb) ? g_part[threadIdx.x] : 0;
    sh[threadIdx.x] = v;
    __syncthreads();
    for (int d = 1; d < 128; d <<= 1) {
        int t = (threadIdx.x >= d) ? sh[threadIdx.x - d] : 0;
        __syncthreads();
        sh[threadIdx.x] += t;
        __syncthreads();
    }
    if (threadIdx.x < nb) g_part[threadIdx.x] = sh[threadIdx.x] - v;  // exclusive
}

__global__ void k_scan3(int n, int E) {
    int i = blockIdx.x * blockDim.x + threadIdx.x;
    if (i < n) {
        g_offs[i] += g_part[i >> 10];
        g_cur[i] = 0;
    }
    if (i == 0) g_offs[n] = E;
}

__global__ void k_fill(const int* __restrict__ row, const int* __restrict__ col, int E) {
    int e = blockIdx.x * blockDim.x + threadIdx.x;
    if (e < E) {
        int c = col[e];
        int p = g_offs[c] + atomicAdd(&g_cur[c], 1);
        g_csr[p] = row[e];
    }
}

// ---------------------------------------------------------------------------
// Fused GEMM v2: 64-node tile, 128 threads. H^T staged in smem [FI][68]
// (padded: conflict-free). W read via __ldg (L1-resident, broadcast).
// Thread tile: 4 contiguous nodes (one LDS.128 per k) x CN = FO/8 outputs.
// MODE 0: in = x raw;                     epilogue: g16 = dinv * (h@W)
// MODE 1: prologue relu(dinv*in + bprev); epilogue: g16 = dinv * dot
// MODE 2: prologue relu(dinv*in + bprev); epilogue: out = dot + bout (fp32)
// ---------------------------------------------------------------------------
template <int FI, int FO, int MODE>
__global__ __launch_bounds__(128)
void k_gemm(const float* __restrict__ in, const float* __restrict__ W,
            const float* __restrict__ bprev, const float* __restrict__ bout,
            __half* __restrict__ g, float* __restrict__ out, int n)
{
    __shared__ float shHT[FI * 68];

    const int tid   = threadIdx.x;
    const int node0 = blockIdx.x * 64;

    // Stage H^T with fused prologue. i = (kc, node), node fastest:
    // writes HT[4kc+j][node] are conflict-free (bank = (4k+node)%32).
    #pragma unroll 2
    for (int i = tid; i < 64 * (FI / 4); i += 128) {
        int node = i & 63;
        int kc   = i >> 6;
        int f    = kc * 4;
        int gn   = node0 + node;
        float4 v = make_float4(0.f, 0.f, 0.f, 0.f);
        float dv = 0.f;
        if (gn < n) {
            v = *(const float4*)(in + (size_t)gn * FI + f);
            if (MODE) dv = g_dinv[gn];
        }
        float t0 = v.x, t1 = v.y, t2 = v.z, t3 = v.w;
        if (MODE) {
            t0 = fmaxf(fmaf(t0, dv, __ldg(bprev + f + 0)), 0.f);
            t1 = fmaxf(fmaf(t1, dv, __ldg(bprev + f + 1)), 0.f);
            t2 = fmaxf(fmaf(t2, dv, __ldg(bprev + f + 2)), 0.f);
            t3 = fmaxf(fmaf(t3, dv, __ldg(bprev + f + 3)), 0.f);
        }
        shHT[(f + 0) * 68 + node] = t0;
        shHT[(f + 1) * 68 + node] = t1;
        shHT[(f + 2) * 68 + node] = t2;
        shHT[(f + 3) * 68 + node] = t3;
    }
    __syncthreads();

    constexpr int CN = FO / 8;
    const int tx = tid & 7;
    const int ty = tid >> 3;
    const int nb = ty * 4;
    const int fb = tx * CN;

    float accr[4][CN];
    #pragma unroll
    for (int r = 0; r < 4; r++)
        #pragma unroll
        for (int c = 0; c < CN; c++) accr[r][c] = 0.f;

    #pragma unroll 4
    for (int k = 0; k < FI; k++) {
        float4 a = *(const float4*)(shHT + k * 68 + nb);
        float wv[CN];
        if (CN == 2) {
            float2 w2 = __ldg((const float2*)(W + (size_t)k * FO + fb));
            wv[0] = w2.x; wv[1] = w2.y;
        } else {
            #pragma unroll
            for (int q = 0; q < CN / 4; q++) {
                float4 w4 = __ldg((const float4*)(W + (size_t)k * FO + fb) + q);
                wv[q * 4 + 0] = w4.x; wv[q * 4 + 1] = w4.y;
                wv[q * 4 + 2] = w4.z; wv[q * 4 + 3] = w4.w;
            }
        }
        #pragma unroll
        for (int c = 0; c < CN; c++) {
            accr[0][c] = fmaf(a.x, wv[c], accr[0][c]);
            accr[1][c] = fmaf(a.y, wv[c], accr[1][c]);
            accr[2][c] = fmaf(a.z, wv[c], accr[2][c]);
            accr[3][c] = fmaf(a.w, wv[c], accr[3][c]);
        }
    }

    #pragma unroll
    for (int r = 0; r < 4; r++) {
        int gn = node0 + nb + r;
        if (gn >= n) continue;
        if (MODE < 2) {
            float dv = g_dinv[gn];
            // pack CN halfs -> vector store
            uint32_t packed[CN / 2];
            #pragma unroll
            for (int h = 0; h < CN / 2; h++) {
                __half2 hh = __floats2half2_rn(accr[r][2 * h] * dv,
                                               accr[r][2 * h + 1] * dv);
                packed[h] = *(uint32_t*)&hh;
            }
            char* dst = (char*)(g + (size_t)gn * FO + fb);
            if (CN == 2) {
                *(uint32_t*)dst = packed[0];
            } else if (CN == 4) {
                *(uint2*)dst = make_uint2(packed[0], packed[1]);
            } else if (CN == 8) {
                *(uint4*)dst = make_uint4(packed[0], packed[1], packed[2], packed[3]);
            } else {  // CN == 16
                ((uint4*)dst)[0] = make_uint4(packed[0], packed[1], packed[2], packed[3]);
                ((uint4*)dst)[1] = make_uint4(packed[4], packed[5], packed[6], packed[7]);
            }
        } else {
            #pragma unroll
            for (int c = 0; c < CN; c++)
                out[(size_t)gn * FO + fb + c] = accr[r][c] + __ldg(bout + fb + c);
        }
    }
}

// ---------------------------------------------------------------------------
// CSR gather-reduce (fp16 source, fp32 accumulate):
// acc[i] = g[i] + sum_{j in N(i)} g[j]
// ---------------------------------------------------------------------------
template <int FO>
__global__ __launch_bounds__(256)
void k_gather(const __half* __restrict__ gsrc, float* __restrict__ acc, int n)
{
    constexpr int HPL = (FO == 128) ? 4 : 2;   // halfs per lane
    constexpr int LPN = FO / HPL;              // lanes per node (<=32)
    constexpr int NPW = 32 / LPN;              // nodes per warp

    int warp = (blockIdx.x * 256 + threadIdx.x) >> 5;
    int lane = threadIdx.x & 31;
    int node = warp * NPW + lane / LPN;
    if (node >= n) return;
    int li  = lane % LPN;
    int beg = g_offs[node];
    int end = g_offs[node + 1];

    const __half* base = gsrc + li * HPL;

    float a[HPL];
    {
        if (HPL == 2) {
            uint32_t u = __ldg((const uint32_t*)(base + (size_t)node * FO));
            float2 f = __half22float2(*(__half2*)&u);
            a[0] = f.x; a[1] = f.y;
        } else {
            uint2 u = __ldg((const uint2*)(base + (size_t)node * FO));
            float2 f0 = __half22float2(*(__half2*)&u.x);
            float2 f1 = __half22float2(*(__half2*)&u.y);
            a[0] = f0.x; a[1] = f0.y; a[2] = f1.x; a[3] = f1.y;
        }
    }

    int e = beg;
    for (; e + 3 < end; e += 4) {
        int s0 = __ldg(g_csr + e + 0);
        int s1 = __ldg(g_csr + e + 1);
        int s2 = __ldg(g_csr + e + 2);
        int s3 = __ldg(g_csr + e + 3);
        if (HPL == 2) {
            uint32_t u0 = __ldg((const uint32_t*)(base + (size_t)s0 * FO));
            uint32_t u1 = __ldg((const uint32_t*)(base + (size_t)s1 * FO));
            uint32_t u2 = __ldg((const uint32_t*)(base + (size_t)s2 * FO));
            uint32_t u3 = __ldg((const uint32_t*)(base + (size_t)s3 * FO));
            float2 f0 = __half22float2(*(__half2*)&u0);
            float2 f1 = __half22float2(*(__half2*)&u1);
            float2 f2 = __half22float2(*(__half2*)&u2);
            float2 f3 = __half22float2(*(__half2*)&u3);
            a[0] += (f0.x + f1.x) + (f2.x + f3.x);
            a[1] += (f0.y + f1.y) + (f2.y + f3.y);
        } else {
            uint2 u0 = __ldg((const uint2*)(base + (size_t)s0 * FO));
            uint2 u1 = __ldg((const uint2*)(base + (size_t)s1 * FO));
            uint2 u2 = __ldg((const uint2*)(base + (size_t)s2 * FO));
            uint2 u3 = __ldg((const uint2*)(base + (size_t)s3 * FO));
            float2 f0a = __half22float2(*(__half2*)&u0.x), f0b = __half22float2(*(__half2*)&u0.y);
            float2 f1a = __half22float2(*(__half2*)&u1.x), f1b = __half22float2(*(__half2*)&u1.y);
            float2 f2a = __half22float2(*(__half2*)&u2.x), f2b = __half22float2(*(__half2*)&u2.y);
            float2 f3a = __half22float2(*(__half2*)&u3.x), f3b = __half22float2(*(__half2*)&u3.y);
            a[0] += (f0a.x + f1a.x) + (f2a.x + f3a.x);
            a[1] += (f0a.y + f1a.y) + (f2a.y + f3a.y);
            a[2] += (f0b.x + f1b.x) + (f2b.x + f3b.x);
            a[3] += (f0b.y + f1b.y) + (f2b.y + f3b.y);
        }
    }
    for (; e < end; e++) {
        int s = __ldg(g_csr + e);
        if (HPL == 2) {
            uint32_t u = __ldg((const uint32_t*)(base + (size_t)s * FO));
            float2 f = __half22float2(*(__half2*)&u);
            a[0] += f.x; a[1] += f.y;
        } else {
            uint2 u = __ldg((const uint2*)(base + (size_t)s * FO));
            float2 f0 = __half22float2(*(__half2*)&u.x);
            float2 f1 = __half22float2(*(__half2*)&u.y);
            a[0] += f0.x; a[1] += f0.y; a[2] += f1.x; a[3] += f1.y;
        }
    }

    float* dst = acc + (size_t)node * FO + li * HPL;
    if (HPL == 2) *(float2*)dst = make_float2(a[0], a[1]);
    else          *(float4*)dst = make_float4(a[0], a[1], a[2], a[3]);
}

// ---------------------------------------------------------------------------
// Host launcher
// ---------------------------------------------------------------------------
template <int FI, int FO, int MODE>
static void launch_gemm(const float* in, const float* W, const float* bprev,
                        const float* bout, __half* g, float* out, int n)
{
    k_gemm<FI, FO, MODE><<<(n + 63) / 64, 128>>>(in, W, bprev, bout, g, out, n);
}

template <int FO>
static void launch_gather(const __half* g, float* acc, int n)
{
    constexpr int HPL = (FO == 128) ? 4 : 2;
    constexpr int NPW = 32 / (FO / HPL);
    int warps  = (n + NPW - 1) / NPW;
    int blocks = (warps + 7) / 8;
    k_gather<FO><<<blocks, 256>>>(g, acc, n);
}

extern "C" void kernel_launch(void* const* d_in, const int* in_sizes, int n_in,
                              void* d_out, int out_size)
{
    const float* x  = (const float*)d_in[0];
    const int*   ei = (const int*)d_in[1];
    const int n = in_sizes[0] / 128;
    const int E = in_sizes[1] / 2;
    const int* row = ei;        // source j
    const int* col = ei + E;    // target i

    const float* W1 = (const float*)d_in[3];  const float* b1 = (const float*)d_in[4];
    const float* W2 = (const float*)d_in[5];  const float* b2 = (const float*)d_in[6];
    const float* W3 = (const float*)d_in[7];  const float* b3 = (const float*)d_in[8];
    const float* W4 = (const float*)d_in[9];  const float* b4 = (const float*)d_in[10];
    const float* W5 = (const float*)d_in[11]; const float* b5 = (const float*)d_in[12];
    const float* W6 = (const float*)d_in[13]; const float* b6 = (const float*)d_in[14];
    const float* Wf = (const float*)d_in[15]; const float* bf = (const float*)d_in[16];

    __half* gptr; float* acc;
    cudaGetSymbolAddress((void**)&gptr, g_gh);
    cudaGetSymbolAddress((void**)&acc, g_acc);
    float* dout = (float*)d_out;

    // Degree + dinv + CSR (recomputed every replay: deterministic, capture-safe)
    k_zero_deg<<<(n + 255) / 256, 256>>>(n);
    k_count<<<(E + 255) / 256, 256>>>(col, E);
    k_dinv<<<(n + 255) / 256, 256>>>(n);
    int nb = (n + 1023) / 1024;
    k_scan1<<<nb, 1024>>>(n);
    k_scan2<<<1, 128>>>(nb);
    k_scan3<<<(n + 255) / 256, 256>>>(n, E);
    k_fill<<<(E + 255) / 256, 256>>>(row, col, E);

    // Layer 1 (128 -> 64)
    launch_gemm<128, 64, 0>(x, W1, nullptr, nullptr, gptr, nullptr, n);
    launch_gather<64>(gptr, acc, n);

    // Layer 2 (64 -> 32)
    launch_gemm<64, 32, 1>(acc, W2, b1, nullptr, gptr, nullptr, n);
    launch_gather<32>(gptr, acc, n);

    // Layer 3 (32 -> 16)
    launch_gemm<32, 16, 1>(acc, W3, b2, nullptr, gptr, nullptr, n);
    launch_gather<16>(gptr, acc, n);

    // Layer 4 (16 -> 32)
    launch_gemm<16, 32, 1>(acc, W4, b3, nullptr, gptr, nullptr, n);
    launch_gather<32>(gptr, acc, n);

    // Layer 5 (32 -> 64)
    launch_gemm<32, 64, 1>(acc, W5, b4, nullptr, gptr, nullptr, n);
    launch_gather<64>(gptr, acc, n);

    // Layer 6 (64 -> 128)
    launch_gemm<64, 128, 1>(acc, W6, b5, nullptr, gptr, nullptr, n);
    launch_gather<128>(gptr, acc, n);

    // Final linear: relu(dinv*acc + b6) @ Wf + bf -> out
    launch_gemm<128, 128, 2>(acc, Wf, b6, bf, nullptr, dout, n);
}

// round 4
// speedup vs baseline: 2.1080x; 1.0067x over previous
#include <cuda_runtime.h>
#include <cuda_fp16.h>
#include <cstdint>
#include <cstddef>

#define MAXN 100000
#define MAXE 3200000

// Scratch (device globals: allocation-free, rewritten every replay)
__device__ __half g_h16a[MAXN * 64];   // fp16 gather source A (max width 64)
__device__ __half g_h16b[MAXN * 16];   // fp16 gather source B (width 16, u4)
__device__ float  g_acc[MAXN * 128];   // fp32 staging
__device__ float  g_acc2[MAXN * 128];  // fp32 staging (layer-6 output)
__device__ float  g_dinv[MAXN];
__device__ int    g_deg[MAXN];
__device__ int    g_offs[MAXN + 1];
__device__ int    g_cur[MAXN];
__device__ int    g_csr[MAXE];         // edge sources grouped by destination
__device__ int    g_part[128];

// ---------------------------------------------------------------------------
// Degree / dinv / CSR build
// ---------------------------------------------------------------------------
__global__ void k_zero_deg(int n) {
    int i = blockIdx.x * blockDim.x + threadIdx.x;
    if (i < n) g_deg[i] = 0;
}

__global__ void k_count(const int* __restrict__ col, int E) {
    int i = blockIdx.x * blockDim.x + threadIdx.x;
    if (i < E) atomicAdd(&g_deg[col[i]], 1);
}

__global__ void k_dinv(int n) {
    int i = blockIdx.x * blockDim.x + threadIdx.x;
    if (i < n) g_dinv[i] = rsqrtf((float)g_deg[i] + 1.0f);  // +1 self loop
}

__global__ __launch_bounds__(1024) void k_scan1(int n) {
    __shared__ int sh[1024];
    int i = blockIdx.x * 1024 + threadIdx.x;
    int v = (i < n) ? g_deg[i] : 0;
    sh[threadIdx.x] = v;
    __syncthreads();
    for (int d = 1; d < 1024; d <<= 1) {
        int t = (threadIdx.x >= d) ? sh[threadIdx.x - d] : 0;
        __syncthreads();
        sh[threadIdx.x] += t;
        __syncthreads();
    }
    if (i < n) g_offs[i] = sh[threadIdx.x] - v;  // exclusive
    if (threadIdx.x == 1023) g_part[blockIdx.x] = sh[1023];
}

__global__ __launch_bounds__(128) void k_scan2(int nb) {
    __shared__ int sh[128];
    int v = (threadIdx.x < nb) ? g_part[threadIdx.x] : 0;
    sh[threadIdx.x] = v;
    __syncthreads();
    for (int d = 1; d < 128; d <<= 1) {
        int t = (threadIdx.x >= d) ? sh[threadIdx.x - d] : 0;
        __syncthreads();
        sh[threadIdx.x] += t;
        __syncthreads();
    }
    if (threadIdx.x < nb) g_part[threadIdx.x] = sh[threadIdx.x] - v;  // exclusive
}

__global__ void k_scan3(int n, int E) {
    int i = blockIdx.x * blockDim.x + threadIdx.x;
    if (i < n) {
        g_offs[i] += g_part[i >> 10];
        g_cur[i] = 0;
    }
    if (i == 0) g_offs[n] = E;
}

__global__ void k_fill(const int* __restrict__ row, const int* __restrict__ col, int E) {
    int e = blockIdx.x * blockDim.x + threadIdx.x;
    if (e < E) {
        int c = col[e];
        int p = g_offs[c] + atomicAdd(&g_cur[c], 1);
        g_csr[p] = row[e];
    }
}

// ---------------------------------------------------------------------------
// Fused GEMM: 64-node tile, 128 threads. H^T staged in smem [FI][68].
// W via __ldg (L2/L1-resident, broadcast).
// PRO 0: use in raw.            PRO 1: relu(dinv*in + bpro)
// EPI 0: g16 = f16(dinv * dot)                         (transform-first)
// EPI 1: u16 = f16(dinv * relu(dinv * dot + bepi))     (aggregate-first chain)
// EPI 2: outf = dot                                    (fp32 plain)
// EPI 3: outf = dot + bepi                             (final)
// ---------------------------------------------------------------------------
template <int FI, int FO, int PRO, int EPI>
__global__ __launch_bounds__(128)
void k_gemm(const float* __restrict__ in, const float* __restrict__ W,
            const float* __restrict__ bpro, const float* __restrict__ bepi,
            __half* __restrict__ outh, float* __restrict__ outf, int n)
{
    __shared__ float shHT[FI * 68];

    const int tid   = threadIdx.x;
    const int node0 = blockIdx.x * 64;

    #pragma unroll 2
    for (int i = tid; i < 64 * (FI / 4); i += 128) {
        int node = i & 63;
        int kc   = i >> 6;
        int f    = kc * 4;
        int gn   = node0 + node;
        float4 v = make_float4(0.f, 0.f, 0.f, 0.f);
        float dv = 0.f;
        if (gn < n) {
            v = *(const float4*)(in + (size_t)gn * FI + f);
            if (PRO) dv = g_dinv[gn];
        }
        float t0 = v.x, t1 = v.y, t2 = v.z, t3 = v.w;
        if (PRO) {
            t0 = fmaxf(fmaf(t0, dv, __ldg(bpro + f + 0)), 0.f);
            t1 = fmaxf(fmaf(t1, dv, __ldg(bpro + f + 1)), 0.f);
            t2 = fmaxf(fmaf(t2, dv, __ldg(bpro + f + 2)), 0.f);
            t3 = fmaxf(fmaf(t3, dv, __ldg(bpro + f + 3)), 0.f);
        }
        shHT[(f + 0) * 68 + node] = t0;
        shHT[(f + 1) * 68 + node] = t1;
        shHT[(f + 2) * 68 + node] = t2;
        shHT[(f + 3) * 68 + node] = t3;
    }
    __syncthreads();

    constexpr int CN = FO / 8;
    const int tx = tid & 7;
    const int ty = tid >> 3;
    const int nb = ty * 4;
    const int fb = tx * CN;

    float accr[4][CN];
    #pragma unroll
    for (int r = 0; r < 4; r++)
        #pragma unroll
        for (int c = 0; c < CN; c++) accr[r][c] = 0.f;

    #pragma unroll 4
    for (int k = 0; k < FI; k++) {
        float4 a = *(const float4*)(shHT + k * 68 + nb);
        float wv[CN];
        if (CN == 2) {
            float2 w2 = __ldg((const float2*)(W + (size_t)k * FO + fb));
            wv[0] = w2.x; wv[1] = w2.y;
        } else {
            #pragma unroll
            for (int q = 0; q < CN / 4; q++) {
                float4 w4 = __ldg((const float4*)(W + (size_t)k * FO + fb) + q);
                wv[q * 4 + 0] = w4.x; wv[q * 4 + 1] = w4.y;
                wv[q * 4 + 2] = w4.z; wv[q * 4 + 3] = w4.w;
            }
        }
        #pragma unroll
        for (int c = 0; c < CN; c++) {
            accr[0][c] = fmaf(a.x, wv[c], accr[0][c]);
            accr[1][c] = fmaf(a.y, wv[c], accr[1][c]);
            accr[2][c] = fmaf(a.z, wv[c], accr[2][c]);
            accr[3][c] = fmaf(a.w, wv[c], accr[3][c]);
        }
    }

    #pragma unroll
    for (int r = 0; r < 4; r++) {
        int gn = node0 + nb + r;
        if (gn >= n) continue;
        if (EPI <= 1) {
            float dv = g_dinv[gn];
            float vals[CN];
            #pragma unroll
            for (int c = 0; c < CN; c++) {
                if (EPI == 0) {
                    vals[c] = accr[r][c] * dv;
                } else {
                    vals[c] = dv * fmaxf(fmaf(accr[r][c], dv, __ldg(bepi + fb + c)), 0.f);
                }
            }
            uint32_t packed[CN / 2];
            #pragma unroll
            for (int h = 0; h < CN / 2; h++) {
                __half2 hh = __floats2half2_rn(vals[2 * h], vals[2 * h + 1]);
                packed[h] = *(uint32_t*)&hh;
            }
            char* dst = (char*)(outh + (size_t)gn * FO + fb);
            if (CN == 2)      *(uint32_t*)dst = packed[0];
            else if (CN == 4) *(uint2*)dst = make_uint2(packed[0], packed[1]);
            else if (CN == 8) *(uint4*)dst = make_uint4(packed[0], packed[1], packed[2], packed[3]);
            else {
                ((uint4*)dst)[0] = make_uint4(packed[0], packed[1], packed[2], packed[3]);
                ((uint4*)dst)[1] = make_uint4(packed[4], packed[5], packed[6], packed[7]);
            }
        } else {
            #pragma unroll
            for (int c = 0; c < CN; c++) {
                float v = accr[r][c];
                if (EPI == 3) v += __ldg(bepi + fb + c);
                outf[(size_t)gn * FO + fb + c] = v;
            }
        }
    }
}

// ---------------------------------------------------------------------------
// CSR gather-reduce (fp16 source, fp32 accumulate): s = src[i] + sum_j src[j]
// GM 0: outf = s (fp32)
// GM 1: outh = f16(dinv * relu(dinv * s + bias))   (emit next u tensor)
// ---------------------------------------------------------------------------
template <int FO, int GM>
__global__ __launch_bounds__(256)
void k_gather(const __half* __restrict__ gsrc, float* __restrict__ outf,
              __half* __restrict__ outh, const float* __restrict__ bias, int n)
{
    constexpr int HPL = (FO >= 64) ? ((FO == 128) ? 4 : 2) : 2;
    constexpr int LPN = FO / HPL;              // lanes per node (<=32)
    constexpr int NPW = 32 / LPN;              // nodes per warp

    int warp = (blockIdx.x * 256 + threadIdx.x) >> 5;
    int lane = threadIdx.x & 31;
    int node = warp * NPW + lane / LPN;
    if (node >= n) return;
    int li  = lane % LPN;
    int beg = g_offs[node];
    int end = g_offs[node + 1];

    const __half* base = gsrc + li * HPL;

    float a[HPL];
    {
        if (HPL == 2) {
            uint32_t u = __ldg((const uint32_t*)(base + (size_t)node * FO));
            float2 f = __half22float2(*(__half2*)&u);
            a[0] = f.x; a[1] = f.y;
        } else {
            uint2 u = __ldg((const uint2*)(base + (size_t)node * FO));
            float2 f0 = __half22float2(*(__half2*)&u.x);
            float2 f1 = __half22float2(*(__half2*)&u.y);
            a[0] = f0.x; a[1] = f0.y; a[2] = f1.x; a[3] = f1.y;
        }
    }

    int e = beg;
    for (; e + 3 < end; e += 4) {
        int s0 = __ldg(g_csr + e + 0);
        int s1 = __ldg(g_csr + e + 1);
        int s2 = __ldg(g_csr + e + 2);
        int s3 = __ldg(g_csr + e + 3);
        if (HPL == 2) {
            uint32_t u0 = __ldg((const uint32_t*)(base + (size_t)s0 * FO));
            uint32_t u1 = __ldg((const uint32_t*)(base + (size_t)s1 * FO));
            uint32_t u2 = __ldg((const uint32_t*)(base + (size_t)s2 * FO));
            uint32_t u3 = __ldg((const uint32_t*)(base + (size_t)s3 * FO));
            float2 f0 = __half22float2(*(__half2*)&u0);
            float2 f1 = __half22float2(*(__half2*)&u1);
            float2 f2 = __half22float2(*(__half2*)&u2);
            float2 f3 = __half22float2(*(__half2*)&u3);
            a[0] += (f0.x + f1.x) + (f2.x + f3.x);
            a[1] += (f0.y + f1.y) + (f2.y + f3.y);
        } else {
            uint2 u0 = __ldg((const uint2*)(base + (size_t)s0 * FO));
            uint2 u1 = __ldg((const uint2*)(base + (size_t)s1 * FO));
            uint2 u2 = __ldg((const uint2*)(base + (size_t)s2 * FO));
            uint2 u3 = __ldg((const uint2*)(base + (size_t)s3 * FO));
            float2 f0a = __half22float2(*(__half2*)&u0.x), f0b = __half22float2(*(__half2*)&u0.y);
            float2 f1a = __half22float2(*(__half2*)&u1.x), f1b = __half22float2(*(__half2*)&u1.y);
            float2 f2a = __half22float2(*(__half2*)&u2.x), f2b = __half22float2(*(__half2*)&u2.y);
            float2 f3a = __half22float2(*(__half2*)&u3.x), f3b = __half22float2(*(__half2*)&u3.y);
            a[0] += (f0a.x + f1a.x) + (f2a.x + f3a.x);
            a[1] += (f0a.y + f1a.y) + (f2a.y + f3a.y);
            a[2] += (f0b.x + f1b.x) + (f2b.x + f3b.x);
            a[3] += (f0b.y + f1b.y) + (f2b.y + f3b.y);
        }
    }
    for (; e < end; e++) {
        int s = __ldg(g_csr + e);
        if (HPL == 2) {
            uint32_t u = __ldg((const uint32_t*)(base + (size_t)s * FO));
            float2 f = __half22float2(*(__half2*)&u);
            a[0] += f.x; a[1] += f.y;
        } else {
            uint2 u = __ldg((const uint2*)(base + (size_t)s * FO));
            float2 f0 = __half22float2(*(__half2*)&u.x);
            float2 f1 = __half22float2(*(__half2*)&u.y);
            a[0] += f0.x; a[1] += f0.y; a[2] += f1.x; a[3] += f1.y;
        }
    }

    if (GM == 0) {
        float* dst = outf + (size_t)node * FO + li * HPL;
        if (HPL == 2) *(float2*)dst = make_float2(a[0], a[1]);
        else          *(float4*)dst = make_float4(a[0], a[1], a[2], a[3]);
    } else {
        float dv = g_dinv[node];
        float v0 = dv * fmaxf(fmaf(a[0], dv, __ldg(bias + li * HPL + 0)), 0.f);
        float v1 = dv * fmaxf(fmaf(a[1], dv, __ldg(bias + li * HPL + 1)), 0.f);
        __half2 hh = __floats2half2_rn(v0, v1);
        *(uint32_t*)(outh + (size_t)node * FO + li * HPL) = *(uint32_t*)&hh;
    }
}

// ---------------------------------------------------------------------------
// Host launcher
// ---------------------------------------------------------------------------
template <int FI, int FO, int PRO, int EPI>
static void launch_gemm(const float* in, const float* W, const float* bpro,
                        const float* bepi, __half* outh, float* outf, int n)
{
    k_gemm<FI, FO, PRO, EPI><<<(n + 63) / 64, 128>>>(in, W, bpro, bepi, outh, outf, n);
}

template <int FO, int GM>
static void launch_gather(const __half* g, float* outf, __half* outh,
                          const float* bias, int n)
{
    constexpr int HPL = (FO == 128) ? 4 : 2;
    constexpr int NPW = 32 / (FO / HPL);
    int warps  = (n + NPW - 1) / NPW;
    int blocks = (warps + 7) / 8;
    k_gather<FO, GM><<<blocks, 256>>>(g, outf, outh, bias, n);
}

extern "C" void kernel_launch(void* const* d_in, const int* in_sizes, int n_in,
                              void* d_out, int out_size)
{
    const float* x  = (const float*)d_in[0];
    const int*   ei = (const int*)d_in[1];
    const int n = in_sizes[0] / 128;
    const int E = in_sizes[1] / 2;
    const int* row = ei;        // source j
    const int* col = ei + E;    // target i

    const float* W1 = (const float*)d_in[3];  const float* b1 = (const float*)d_in[4];
    const float* W2 = (const float*)d_in[5];  const float* b2 = (const float*)d_in[6];
    const float* W3 = (const float*)d_in[7];  const float* b3 = (const float*)d_in[8];
    const float* W4 = (const float*)d_in[9];  const float* b4 = (const float*)d_in[10];
    const float* W5 = (const float*)d_in[11]; const float* b5 = (const float*)d_in[12];
    const float* W6 = (const float*)d_in[13]; const float* b6 = (const float*)d_in[14];
    const float* Wf = (const float*)d_in[15]; const float* bf = (const float*)d_in[16];

    __half *A16, *B16; float *acc, *acc2;
    cudaGetSymbolAddress((void**)&A16, g_h16a);
    cudaGetSymbolAddress((void**)&B16, g_h16b);
    cudaGetSymbolAddress((void**)&acc, g_acc);
    cudaGetSymbolAddress((void**)&acc2, g_acc2);
    float* dout = (float*)d_out;

    // Degree + dinv + CSR (recomputed every replay: deterministic, capture-safe)
    k_zero_deg<<<(n + 255) / 256, 256>>>(n);
    k_count<<<(E + 255) / 256, 256>>>(col, E);
    k_dinv<<<(n + 255) / 256, 256>>>(n);
    int nb = (n + 1023) / 1024;
    k_scan1<<<nb, 1024>>>(n);
    k_scan2<<<1, 128>>>(nb);
    k_scan3<<<(n + 255) / 256, 256>>>(n, E);
    k_fill<<<(E + 255) / 256, 256>>>(row, col, E);

    // L1 (128->64, transform-first): g = dinv*(x@W1)
    launch_gemm<128, 64, 0, 0>(x, W1, nullptr, nullptr, A16, nullptr, n);
    launch_gather<64, 0>(A16, acc, nullptr, nullptr, n);

    // L2 (64->32, transform-first): prologue relu(dinv*acc+b1)
    launch_gemm<64, 32, 1, 0>(acc, W2, b1, nullptr, A16, nullptr, n);
    launch_gather<32, 0>(A16, acc, nullptr, nullptr, n);

    // L3 (32->16, transform-first); gather emits u4 = f16(dinv*relu(dinv*s+b3))
    launch_gemm<32, 16, 1, 0>(acc, W3, b2, nullptr, A16, nullptr, n);
    launch_gather<16, 1>(A16, nullptr, B16, b3, n);

    // L4 (16->32, aggregate-first): gather u4 -> s4; GEMM emits u5 (epi b4)
    launch_gather<16, 0>(B16, acc, nullptr, nullptr, n);
    launch_gemm<16, 32, 0, 1>(acc, W4, nullptr, b4, A16, nullptr, n);

    // L5 (32->64, aggregate-first): gather u5 -> s5; GEMM emits u6 (epi b5)
    launch_gather<32, 0>(A16, acc, nullptr, nullptr, n);
    launch_gemm<32, 64, 0, 1>(acc, W5, nullptr, b5, A16, nullptr, n);

    // L6 (64->128, aggregate-first): gather u6 -> s6; GEMM plain fp32 -> acc2
    launch_gather<64, 0>(A16, acc, nullptr, nullptr, n);
    launch_gemm<64, 128, 0, 2>(acc, W6, nullptr, nullptr, nullptr, acc2, n);

    // Final: relu(dinv*acc2 + b6) @ Wf + bf -> out
    launch_gemm<128, 128, 1, 3>(acc2, Wf, b6, bf, nullptr, dout, n);
}

// round 5
// speedup vs baseline: 4.2851x; 2.0328x over previous
#include <cuda_runtime.h>
#include <cuda_fp16.h>
#include <cstdint>
#include <cstddef>

#define MAXN 100000
#define MAXE 3200000

// Scratch (device globals: allocation-free, rewritten every replay)
__device__ __half g_h16a[MAXN * 64];   // fp16 gather source A (max width 64)
__device__ __half g_h16b[MAXN * 16];   // fp16 gather source B (width 16, u4)
__device__ float  g_acc[MAXN * 128];   // fp32 staging
__device__ float  g_acc2[MAXN * 128];  // fp32 staging (layer-6 output)
__device__ float  g_dinv[MAXN];
__device__ int    g_deg[MAXN];
__device__ int    g_offs[MAXN + 1];
__device__ int    g_cur[MAXN];
__device__ int    g_csr[MAXE];         // edge sources grouped by destination
__device__ int    g_part[128];

__device__ __forceinline__ uint32_t smem_u32(const void* p) {
    return (uint32_t)__cvta_generic_to_shared(p);
}

// ---------------------------------------------------------------------------
// Degree / dinv / CSR build
// ---------------------------------------------------------------------------
__global__ void k_zero_deg(int n) {
    int i = blockIdx.x * blockDim.x + threadIdx.x;
    if (i < n) g_deg[i] = 0;
}

__global__ void k_count(const int* __restrict__ col, int E) {
    int i = blockIdx.x * blockDim.x + threadIdx.x;
    if (i < E) atomicAdd(&g_deg[col[i]], 1);
}

__global__ void k_dinv(int n) {
    int i = blockIdx.x * blockDim.x + threadIdx.x;
    if (i < n) g_dinv[i] = rsqrtf((float)g_deg[i] + 1.0f);  // +1 self loop
}

__global__ __launch_bounds__(1024) void k_scan1(int n) {
    __shared__ int sh[1024];
    int i = blockIdx.x * 1024 + threadIdx.x;
    int v = (i < n) ? g_deg[i] : 0;
    sh[threadIdx.x] = v;
    __syncthreads();
    for (int d = 1; d < 1024; d <<= 1) {
        int t = (threadIdx.x >= d) ? sh[threadIdx.x - d] : 0;
        __syncthreads();
        sh[threadIdx.x] += t;
        __syncthreads();
    }
    if (i < n) g_offs[i] = sh[threadIdx.x] - v;  // exclusive
    if (threadIdx.x == 1023) g_part[blockIdx.x] = sh[1023];
}

__global__ __launch_bounds__(128) void k_scan2(int nb) {
    __shared__ int sh[128];
    int v = (threadIdx.x < nb) ? g_part[threadIdx.x] : 0;
    sh[threadIdx.x] = v;
    __syncthreads();
    for (int d = 1; d < 128; d <<= 1) {
        int t = (threadIdx.x >= d) ? sh[threadIdx.x - d] : 0;
        __syncthreads();
        sh[threadIdx.x] += t;
        __syncthreads();
    }
    if (threadIdx.x < nb) g_part[threadIdx.x] = sh[threadIdx.x] - v;  // exclusive
}

__global__ void k_scan3(int n, int E) {
    int i = blockIdx.x * blockDim.x + threadIdx.x;
    if (i < n) {
        g_offs[i] += g_part[i >> 10];
        g_cur[i] = 0;
    }
    if (i == 0) g_offs[n] = E;
}

__global__ void k_fill(const int* __restrict__ row, const int* __restrict__ col, int E) {
    int e = blockIdx.x * blockDim.x + threadIdx.x;
    if (e < E) {
        int c = col[e];
        int p = g_offs[c] + atomicAdd(&g_cur[c], 1);
        g_csr[p] = row[e];
    }
}

// ---------------------------------------------------------------------------
// Tensor-core GEMM (mma.sync m16n8k16, f16 x f16 -> f32).
// Block = 128 threads (4 warps), tile = 64 nodes x FO. A,W staged fp16 in smem.
// PRO 0: in raw.               PRO 1: relu(dinv*in + bpro)
// EPI 0: outh = f16(dinv * dot)
// EPI 1: outh = f16(dinv * relu(dinv * dot + bepi))
// EPI 2: outf = dot
// EPI 3: outf = dot + bepi
// ---------------------------------------------------------------------------
template <int FI, int FO, int PRO, int EPI>
__global__ __launch_bounds__(128)
void k_tgemm(const float* __restrict__ in, const float* __restrict__ W,
             const float* __restrict__ bpro, const float* __restrict__ bepi,
             __half* __restrict__ outh, float* __restrict__ outf, int n)
{
    constexpr int SA = FI + 8;   // A row stride (halves): +16B pad, conflict-free ldmatrix
    constexpr int SW = FO + 8;   // W row stride (halves)
    extern __shared__ char smraw[];
    __half* sA = (__half*)smraw;            // 64 x SA
    __half* sW = (__half*)smraw + 64 * SA;  // FI x SW

    const int tid   = threadIdx.x;
    const int node0 = blockIdx.x * 64;

    // Stage A (64 x FI), fp32 -> fp16, fused prologue. Coalesced: i = node*(FI/4)+fc.
    for (int i = tid; i < 64 * (FI / 4); i += 128) {
        int node = i / (FI / 4);
        int fc   = i % (FI / 4);
        int f    = fc * 4;
        int gn   = node0 + node;
        float4 v = make_float4(0.f, 0.f, 0.f, 0.f);
        float dv = 0.f;
        if (gn < n) {
            v = *(const float4*)(in + (size_t)gn * FI + f);
            if (PRO) dv = g_dinv[gn];
        }
        float t0 = v.x, t1 = v.y, t2 = v.z, t3 = v.w;
        if (PRO) {
            t0 = fmaxf(fmaf(t0, dv, __ldg(bpro + f + 0)), 0.f);
            t1 = fmaxf(fmaf(t1, dv, __ldg(bpro + f + 1)), 0.f);
            t2 = fmaxf(fmaf(t2, dv, __ldg(bpro + f + 2)), 0.f);
            t3 = fmaxf(fmaf(t3, dv, __ldg(bpro + f + 3)), 0.f);
        }
        __half2 h01 = __floats2half2_rn(t0, t1);
        __half2 h23 = __floats2half2_rn(t2, t3);
        *(uint2*)(sA + node * SA + f) = make_uint2(*(uint32_t*)&h01, *(uint32_t*)&h23);
    }
    // Stage W (FI x FO), fp32 -> fp16
    for (int i = tid; i < FI * (FO / 4); i += 128) {
        int k  = i / (FO / 4);
        int nc = i % (FO / 4);
        int nn = nc * 4;
        float4 w = __ldg((const float4*)(W + (size_t)k * FO + nn));
        __half2 h01 = __floats2half2_rn(w.x, w.y);
        __half2 h23 = __floats2half2_rn(w.z, w.w);
        *(uint2*)(sW + k * SW + nn) = make_uint2(*(uint32_t*)&h01, *(uint32_t*)&h23);
    }
    __syncthreads();

    const int w    = tid >> 5;
    const int lane = tid & 31;
    constexpr int NT = FO / 8;

    float acc[NT][4];
    #pragma unroll
    for (int t = 0; t < NT; t++) {
        acc[t][0] = 0.f; acc[t][1] = 0.f; acc[t][2] = 0.f; acc[t][3] = 0.f;
    }

    const uint32_t aBase = smem_u32(sA);
    const uint32_t wBase = smem_u32(sW);
    // A ldmatrix x4: row = w*16 + (lane&15), col = kk*16 + (lane>>4)*8
    const int arow = w * 16 + (lane & 15);
    const int asel = (lane >> 4) * 8;

    #pragma unroll
    for (int kk = 0; kk < FI / 16; kk++) {
        uint32_t a0, a1, a2, a3;
        {
            uint32_t addrA = aBase + (uint32_t)((arow * SA + kk * 16 + asel) * 2);
            asm volatile("ldmatrix.sync.aligned.m8n8.x4.shared.b16 {%0,%1,%2,%3}, [%4];"
                         : "=r"(a0), "=r"(a1), "=r"(a2), "=r"(a3) : "r"(addrA));
        }
        const int krow = kk * 16 + (lane & 15);
        #pragma unroll
        for (int nt = 0; nt < NT; nt++) {
            uint32_t b0, b1;
            uint32_t addrB = wBase + (uint32_t)((krow * SW + nt * 8) * 2);
            asm volatile("ldmatrix.sync.aligned.m8n8.x2.trans.shared.b16 {%0,%1}, [%2];"
                         : "=r"(b0), "=r"(b1) : "r"(addrB));
            asm volatile("mma.sync.aligned.m16n8k16.row.col.f32.f16.f16.f32 "
                         "{%0,%1,%2,%3}, {%4,%5,%6,%7}, {%8,%9}, {%0,%1,%2,%3};"
                         : "+f"(acc[nt][0]), "+f"(acc[nt][1]),
                           "+f"(acc[nt][2]), "+f"(acc[nt][3])
                         : "r"(a0), "r"(a1), "r"(a2), "r"(a3), "r"(b0), "r"(b1));
        }
    }

    // Epilogue. C frag: c0,c1 -> (row g, col 2t..2t+1); c2,c3 -> (row g+8, same cols)
    const int g8 = lane >> 2;
    const int t2 = (lane & 3) * 2;
    const int r0 = node0 + w * 16 + g8;
    const int r1 = r0 + 8;
    float dv0 = 0.f, dv1 = 0.f;
    if (EPI <= 1) {
        if (r0 < n) dv0 = g_dinv[r0];
        if (r1 < n) dv1 = g_dinv[r1];
    }
    #pragma unroll
    for (int nt = 0; nt < NT; nt++) {
        int c = nt * 8 + t2;
        float d0 = acc[nt][0], d1 = acc[nt][1], d2 = acc[nt][2], d3 = acc[nt][3];
        if (EPI == 0) {
            if (r0 < n) {
                __half2 hh = __floats2half2_rn(d0 * dv0, d1 * dv0);
                *(uint32_t*)(outh + (size_t)r0 * FO + c) = *(uint32_t*)&hh;
            }
            if (r1 < n) {
                __half2 hh = __floats2half2_rn(d2 * dv1, d3 * dv1);
                *(uint32_t*)(outh + (size_t)r1 * FO + c) = *(uint32_t*)&hh;
            }
        } else if (EPI == 1) {
            float bc0 = __ldg(bepi + c), bc1 = __ldg(bepi + c + 1);
            if (r0 < n) {
                float v0 = dv0 * fmaxf(fmaf(d0, dv0, bc0), 0.f);
                float v1 = dv0 * fmaxf(fmaf(d1, dv0, bc1), 0.f);
                __half2 hh = __floats2half2_rn(v0, v1);
                *(uint32_t*)(outh + (size_t)r0 * FO + c) = *(uint32_t*)&hh;
            }
            if (r1 < n) {
                float v0 = dv1 * fmaxf(fmaf(d2, dv1, bc0), 0.f);
                float v1 = dv1 * fmaxf(fmaf(d3, dv1, bc1), 0.f);
                __half2 hh = __floats2half2_rn(v0, v1);
                *(uint32_t*)(outh + (size_t)r1 * FO + c) = *(uint32_t*)&hh;
            }
        } else {
            float add0 = 0.f, add1 = 0.f;
            if (EPI == 3) { add0 = __ldg(bepi + c); add1 = __ldg(bepi + c + 1); }
            if (r0 < n) *(float2*)(outf + (size_t)r0 * FO + c) = make_float2(d0 + add0, d1 + add1);
            if (r1 < n) *(float2*)(outf + (size_t)r1 * FO + c) = make_float2(d2 + add0, d3 + add1);
        }
    }
}

// ---------------------------------------------------------------------------
// CSR gather-reduce (fp16 source, fp32 accumulate): s = src[i] + sum_j src[j]
// Indices fetched 4-at-a-time via uniform int4 LDG (1 LDG per 4 edges).
// GM 0: outf = s (fp32)
// GM 1: outh = f16(dinv * relu(dinv * s + bias))
// ---------------------------------------------------------------------------
template <int FO, int GM>
__global__ __launch_bounds__(256)
void k_gather(const __half* __restrict__ gsrc, float* __restrict__ outf,
              __half* __restrict__ outh, const float* __restrict__ bias, int n)
{
    constexpr int HPL = (FO == 128) ? 4 : 2;   // halves per lane
    constexpr int LPN = FO / HPL;              // lanes per node (<=32)
    constexpr int NPW = 32 / LPN;              // nodes per warp

    int warp = (blockIdx.x * 256 + threadIdx.x) >> 5;
    int lane = threadIdx.x & 31;
    int node = warp * NPW + lane / LPN;
    if (node >= n) return;
    int li  = lane % LPN;
    int beg = g_offs[node];
    int end = g_offs[node + 1];

    const __half* base = gsrc + li * HPL;

    float a[HPL];
    {
        if (HPL == 2) {
            uint32_t u = __ldg((const uint32_t*)(base + (size_t)node * FO));
            float2 f = __half22float2(*(__half2*)&u);
            a[0] = f.x; a[1] = f.y;
        } else {
            uint2 u = __ldg((const uint2*)(base + (size_t)node * FO));
            float2 f0 = __half22float2(*(__half2*)&u.x);
            float2 f1 = __half22float2(*(__half2*)&u.y);
            a[0] = f0.x; a[1] = f0.y; a[2] = f1.x; a[3] = f1.y;
        }
    }

    auto accum1 = [&](int s) {
        if (HPL == 2) {
            uint32_t u = __ldg((const uint32_t*)(base + (size_t)s * FO));
            float2 f = __half22float2(*(__half2*)&u);
            a[0] += f.x; a[1] += f.y;
        } else {
            uint2 u = __ldg((const uint2*)(base + (size_t)s * FO));
            float2 f0 = __half22float2(*(__half2*)&u.x);
            float2 f1 = __half22float2(*(__half2*)&u.y);
            a[0] += f0.x; a[1] += f0.y; a[2] += f1.x; a[3] += f1.y;
        }
    };

    int e = beg;
    // Peel to 16B alignment of the index stream
    while (e < end && (e & 3)) { accum1(__ldg(g_csr + e)); e++; }

    for (; e + 3 < end; e += 4) {
        int4 iv = __ldg((const int4*)(g_csr + e));   // uniform in node-group: 1 LDG
        if (HPL == 2) {
            uint32_t u0 = __ldg((const uint32_t*)(base + (size_t)iv.x * FO));
            uint32_t u1 = __ldg((const uint32_t*)(base + (size_t)iv.y * FO));
            uint32_t u2 = __ldg((const uint32_t*)(base + (size_t)iv.z * FO));
            uint32_t u3 = __ldg((const uint32_t*)(base + (size_t)iv.w * FO));
            float2 f0 = __half22float2(*(__half2*)&u0);
            float2 f1 = __half22float2(*(__half2*)&u1);
            float2 f2 = __half22float2(*(__half2*)&u2);
            float2 f3 = __half22float2(*(__half2*)&u3);
            a[0] += (f0.x + f1.x) + (f2.x + f3.x);
            a[1] += (f0.y + f1.y) + (f2.y + f3.y);
        } else {
            uint2 u0 = __ldg((const uint2*)(base + (size_t)iv.x * FO));
            uint2 u1 = __ldg((const uint2*)(base + (size_t)iv.y * FO));
            uint2 u2 = __ldg((const uint2*)(base + (size_t)iv.z * FO));
            uint2 u3 = __ldg((const uint2*)(base + (size_t)iv.w * FO));
            float2 f0a = __half22float2(*(__half2*)&u0.x), f0b = __half22float2(*(__half2*)&u0.y);
            float2 f1a = __half22float2(*(__half2*)&u1.x), f1b = __half22float2(*(__half2*)&u1.y);
            float2 f2a = __half22float2(*(__half2*)&u2.x), f2b = __half22float2(*(__half2*)&u2.y);
            float2 f3a = __half22float2(*(__half2*)&u3.x), f3b = __half22float2(*(__half2*)&u3.y);
            a[0] += (f0a.x + f1a.x) + (f2a.x + f3a.x);
            a[1] += (f0a.y + f1a.y) + (f2a.y + f3a.y);
            a[2] += (f0b.x + f1b.x) + (f2b.x + f3b.x);
            a[3] += (f0b.y + f1b.y) + (f2b.y + f3b.y);
        }
    }
    for (; e < end; e++) accum1(__ldg(g_csr + e));

    if (GM == 0) {
        float* dst = outf + (size_t)node * FO + li * HPL;
        if (HPL == 2) *(float2*)dst = make_float2(a[0], a[1]);
        else          *(float4*)dst = make_float4(a[0], a[1], a[2], a[3]);
    } else {
        float dv = g_dinv[node];
        float v0 = dv * fmaxf(fmaf(a[0], dv, __ldg(bias + li * HPL + 0)), 0.f);
        float v1 = dv * fmaxf(fmaf(a[1], dv, __ldg(bias + li * HPL + 1)), 0.f);
        __half2 hh = __floats2half2_rn(v0, v1);
        *(uint32_t*)(outh + (size_t)node * FO + li * HPL) = *(uint32_t*)&hh;
    }
}

// ---------------------------------------------------------------------------
// Host launcher
// ---------------------------------------------------------------------------
template <int FI, int FO, int PRO, int EPI>
static void launch_tgemm(const float* in, const float* W, const float* bpro,
                         const float* bepi, __half* outh, float* outf, int n)
{
    constexpr int SM = (64 * (FI + 8) + FI * (FO + 8)) * 2;
    cudaFuncSetAttribute((const void*)k_tgemm<FI, FO, PRO, EPI>,
                         cudaFuncAttributeMaxDynamicSharedMemorySize, SM);
    k_tgemm<FI, FO, PRO, EPI><<<(n + 63) / 64, 128, SM>>>(in, W, bpro, bepi, outh, outf, n);
}

template <int FO, int GM>
static void launch_gather(const __half* g, float* outf, __half* outh,
                          const float* bias, int n)
{
    constexpr int HPL = (FO == 128) ? 4 : 2;
    constexpr int NPW = 32 / (FO / HPL);
    int warps  = (n + NPW - 1) / NPW;
    int blocks = (warps + 7) / 8;
    k_gather<FO, GM><<<blocks, 256>>>(g, outf, outh, bias, n);
}

extern "C" void kernel_launch(void* const* d_in, const int* in_sizes, int n_in,
                              void* d_out, int out_size)
{
    const float* x  = (const float*)d_in[0];
    const int*   ei = (const int*)d_in[1];
    const int n = in_sizes[0] / 128;
    const int E = in_sizes[1] / 2;
    const int* row = ei;        // source j
    const int* col = ei + E;    // target i

    const float* W1 = (const float*)d_in[3];  const float* b1 = (const float*)d_in[4];
    const float* W2 = (const float*)d_in[5];  const float* b2 = (const float*)d_in[6];
    const float* W3 = (const float*)d_in[7];  const float* b3 = (const float*)d_in[8];
    const float* W4 = (const float*)d_in[9];  const float* b4 = (const float*)d_in[10];
    const float* W5 = (const float*)d_in[11]; const float* b5 = (const float*)d_in[12];
    const float* W6 = (const float*)d_in[13]; const float* b6 = (const float*)d_in[14];
    const float* Wf = (const float*)d_in[15]; const float* bf = (const float*)d_in[16];

    __half *A16, *B16; float *acc, *acc2;
    cudaGetSymbolAddress((void**)&A16, g_h16a);
    cudaGetSymbolAddress((void**)&B16, g_h16b);
    cudaGetSymbolAddress((void**)&acc, g_acc);
    cudaGetSymbolAddress((void**)&acc2, g_acc2);
    float* dout = (float*)d_out;

    // Degree + dinv + CSR (recomputed every replay: deterministic, capture-safe)
    k_zero_deg<<<(n + 255) / 256, 256>>>(n);
    k_count<<<(E + 255) / 256, 256>>>(col, E);
    k_dinv<<<(n + 255) / 256, 256>>>(n);
    int nb = (n + 1023) / 1024;
    k_scan1<<<nb, 1024>>>(n);
    k_scan2<<<1, 128>>>(nb);
    k_scan3<<<(n + 255) / 256, 256>>>(n, E);
    k_fill<<<(E + 255) / 256, 256>>>(row, col, E);

    // L1 (128->64, transform-first): g = dinv*(x@W1)
    launch_tgemm<128, 64, 0, 0>(x, W1, nullptr, nullptr, A16, nullptr, n);
    launch_gather<64, 0>(A16, acc, nullptr, nullptr, n);

    // L2 (64->32, transform-first): prologue relu(dinv*acc+b1)
    launch_tgemm<64, 32, 1, 0>(acc, W2, b1, nullptr, A16, nullptr, n);
    launch_gather<32, 0>(A16, acc, nullptr, nullptr, n);

    // L3 (32->16, transform-first); gather emits u4 = f16(dinv*relu(dinv*s+b3))
    launch_tgemm<32, 16, 1, 0>(acc, W3, b2, nullptr, A16, nullptr, n);
    launch_gather<16, 1>(A16, nullptr, B16, b3, n);

    // L4 (16->32, aggregate-first): gather u4 -> s4; GEMM emits u5 (epi b4)
    launch_gather<16, 0>(B16, acc, nullptr, nullptr, n);
    launch_tgemm<16, 32, 0, 1>(acc, W4, nullptr, b4, A16, nullptr, n);

    // L5 (32->64, aggregate-first): gather u5 -> s5; GEMM emits u6 (epi b5)
    launch_gather<32, 0>(A16, acc, nullptr, nullptr, n);
    launch_tgemm<32, 64, 0, 1>(acc, W5, nullptr, b5, A16, nullptr, n);

    // L6 (64->128, aggregate-first): gather u6 -> s6; GEMM plain fp32 -> acc2
    launch_gather<64, 0>(A16, acc, nullptr, nullptr, n);
    launch_tgemm<64, 128, 0, 2>(acc, W6, nullptr, nullptr, nullptr, acc2, n);

    // Final: relu(dinv*acc2 + b6) @ Wf + bf -> out
    launch_tgemm<128, 128, 1, 3>(acc2, Wf, b6, bf, nullptr, dout, n);
}

// round 6
// speedup vs baseline: 4.4083x; 1.0287x over previous
#include <cuda_runtime.h>
#include <cuda_fp16.h>
#include <cstdint>
#include <cstddef>

#define MAXN 100000
#define MAXE 3200000

// Scratch (device globals: allocation-free, rewritten every replay)
__device__ __half g_bufA[MAXN * 128];  // fp16 ping
__device__ __half g_bufB[MAXN * 128];  // fp16 pong
__device__ float  g_dinv[MAXN];
__device__ int    g_deg[MAXN];
__device__ int    g_offs[MAXN + 1];
__device__ int    g_cur[MAXN];
__device__ int    g_csr[MAXE];         // edge sources grouped by destination
__device__ int    g_part[128];

__device__ __forceinline__ uint32_t smem_u32(const void* p) {
    return (uint32_t)__cvta_generic_to_shared(p);
}

// ---------------------------------------------------------------------------
// Degree / dinv / CSR build
// ---------------------------------------------------------------------------
__global__ void k_zero(int n) {
    int i = blockIdx.x * blockDim.x + threadIdx.x;
    if (i < n) { g_deg[i] = 0; g_cur[i] = 0; }
}

__global__ void k_count(const int* __restrict__ col, int E) {
    int i = blockIdx.x * blockDim.x + threadIdx.x;
    if (i < E) atomicAdd(&g_deg[col[i]], 1);
}

__global__ __launch_bounds__(1024) void k_scan1(int n) {
    __shared__ int sh[1024];
    int i = blockIdx.x * 1024 + threadIdx.x;
    int v = (i < n) ? g_deg[i] : 0;
    sh[threadIdx.x] = v;
    __syncthreads();
    for (int d = 1; d < 1024; d <<= 1) {
        int t = (threadIdx.x >= d) ? sh[threadIdx.x - d] : 0;
        __syncthreads();
        sh[threadIdx.x] += t;
        __syncthreads();
    }
    if (i < n) g_offs[i] = sh[threadIdx.x] - v;  // exclusive
    if (threadIdx.x == 1023) g_part[blockIdx.x] = sh[1023];
}

__global__ __launch_bounds__(128) void k_scan2(int nb) {
    __shared__ int sh[128];
    int v = (threadIdx.x < nb) ? g_part[threadIdx.x] : 0;
    sh[threadIdx.x] = v;
    __syncthreads();
    for (int d = 1; d < 128; d <<= 1) {
        int t = (threadIdx.x >= d) ? sh[threadIdx.x - d] : 0;
        __syncthreads();
        sh[threadIdx.x] += t;
        __syncthreads();
    }
    if (threadIdx.x < nb) g_part[threadIdx.x] = sh[threadIdx.x] - v;  // exclusive
}

// offs += block offset; dinv = rsqrt(deg+1); sentinel
__global__ void k_scan3(int n, int E) {
    int i = blockIdx.x * blockDim.x + threadIdx.x;
    if (i < n) {
        g_offs[i] += g_part[i >> 10];
        g_dinv[i] = rsqrtf((float)g_deg[i] + 1.0f);
    }
    if (i == 0) g_offs[n] = E;
}

__global__ void k_fill(const int* __restrict__ row, const int* __restrict__ col, int E) {
    int e = blockIdx.x * blockDim.x + threadIdx.x;
    if (e < E) {
        int c = col[e];
        int p = g_offs[c] + atomicAdd(&g_cur[c], 1);
        g_csr[p] = row[e];
    }
}

// ---------------------------------------------------------------------------
// Tensor-core GEMM (mma.sync m16n8k16, f16 x f16 -> f32).
// Block = 128 threads (4 warps), tile = 64 nodes x FO.
// PRO 0: A = fp16 input raw.     PRO 2: A = f16(dinv * fp32 input)   (L1)
// EPI 0: outh = f16(dot)                          (pure, dinv folded into A)
// EPI 1: outh = f16(dinv * relu(dinv * dot + bepi))   (next-u, AF layers)
// EPI 2: outh = f16(relu(dinv * dot + bepi))          (L6 -> final linear in)
// EPI 3: outf = dot + bepi                            (final, fp32)
// ---------------------------------------------------------------------------
template <int FI, int FO, int PRO, int EPI>
__global__ __launch_bounds__(128)
void k_tgemm(const __half* __restrict__ inh, const float* __restrict__ inf,
             const float* __restrict__ W, const float* __restrict__ bepi,
             __half* __restrict__ outh, float* __restrict__ outf, int n)
{
    constexpr int SA = FI + 8;   // A row stride (halves): +16B pad, conflict-free ldmatrix
    constexpr int SW = FO + 8;   // W row stride (halves)
    extern __shared__ char smraw[];
    __half* sA = (__half*)smraw;            // 64 x SA
    __half* sW = (__half*)smraw + 64 * SA;  // FI x SW

    const int tid   = threadIdx.x;
    const int node0 = blockIdx.x * 64;

    if (PRO == 0) {
        // A is fp16: straight vector copy (uint4 = 8 halves)
        for (int i = tid; i < 64 * (FI / 8); i += 128) {
            int node = i / (FI / 8);
            int f8   = i % (FI / 8);
            int gn   = node0 + node;
            uint4 v = make_uint4(0, 0, 0, 0);
            if (gn < n) v = *(const uint4*)(inh + (size_t)gn * FI + f8 * 8);
            *(uint4*)(sA + node * SA + f8 * 8) = v;
        }
    } else {
        // A = f16(dinv * fp32 input)
        for (int i = tid; i < 64 * (FI / 4); i += 128) {
            int node = i / (FI / 4);
            int fc   = i % (FI / 4);
            int f    = fc * 4;
            int gn   = node0 + node;
            float4 v = make_float4(0.f, 0.f, 0.f, 0.f);
            float dv = 0.f;
            if (gn < n) {
                v = *(const float4*)(inf + (size_t)gn * FI + f);
                dv = g_dinv[gn];
            }
            __half2 h01 = __floats2half2_rn(v.x * dv, v.y * dv);
            __half2 h23 = __floats2half2_rn(v.z * dv, v.w * dv);
            *(uint2*)(sA + node * SA + f) = make_uint2(*(uint32_t*)&h01, *(uint32_t*)&h23);
        }
    }
    // Stage W (FI x FO), fp32 -> fp16
    for (int i = tid; i < FI * (FO / 4); i += 128) {
        int k  = i / (FO / 4);
        int nc = i % (FO / 4);
        int nn = nc * 4;
        float4 w = __ldg((const float4*)(W + (size_t)k * FO + nn));
        __half2 h01 = __floats2half2_rn(w.x, w.y);
        __half2 h23 = __floats2half2_rn(w.z, w.w);
        *(uint2*)(sW + k * SW + nn) = make_uint2(*(uint32_t*)&h01, *(uint32_t*)&h23);
    }
    __syncthreads();

    const int w    = tid >> 5;
    const int lane = tid & 31;
    constexpr int NT = FO / 8;

    float acc[NT][4];
    #pragma unroll
    for (int t = 0; t < NT; t++) {
        acc[t][0] = 0.f; acc[t][1] = 0.f; acc[t][2] = 0.f; acc[t][3] = 0.f;
    }

    const uint32_t aBase = smem_u32(sA);
    const uint32_t wBase = smem_u32(sW);
    const int arow = w * 16 + (lane & 15);
    const int asel = (lane >> 4) * 8;

    #pragma unroll
    for (int kk = 0; kk < FI / 16; kk++) {
        uint32_t a0, a1, a2, a3;
        {
            uint32_t addrA = aBase + (uint32_t)((arow * SA + kk * 16 + asel) * 2);
            asm volatile("ldmatrix.sync.aligned.m8n8.x4.shared.b16 {%0,%1,%2,%3}, [%4];"
                         : "=r"(a0), "=r"(a1), "=r"(a2), "=r"(a3) : "r"(addrA));
        }
        const int krow = kk * 16 + (lane & 15);
        #pragma unroll
        for (int nt = 0; nt < NT; nt++) {
            uint32_t b0, b1;
            uint32_t addrB = wBase + (uint32_t)((krow * SW + nt * 8) * 2);
            asm volatile("ldmatrix.sync.aligned.m8n8.x2.trans.shared.b16 {%0,%1}, [%2];"
                         : "=r"(b0), "=r"(b1) : "r"(addrB));
            asm volatile("mma.sync.aligned.m16n8k16.row.col.f32.f16.f16.f32 "
                         "{%0,%1,%2,%3}, {%4,%5,%6,%7}, {%8,%9}, {%0,%1,%2,%3};"
                         : "+f"(acc[nt][0]), "+f"(acc[nt][1]),
                           "+f"(acc[nt][2]), "+f"(acc[nt][3])
                         : "r"(a0), "r"(a1), "r"(a2), "r"(a3), "r"(b0), "r"(b1));
        }
    }

    // Epilogue. C frag: c0,c1 -> (row g, col 2t..2t+1); c2,c3 -> (row g+8)
    const int g8 = lane >> 2;
    const int t2 = (lane & 3) * 2;
    const int r0 = node0 + w * 16 + g8;
    const int r1 = r0 + 8;
    float dv0 = 0.f, dv1 = 0.f;
    if (EPI == 1 || EPI == 2) {
        if (r0 < n) dv0 = g_dinv[r0];
        if (r1 < n) dv1 = g_dinv[r1];
    }
    #pragma unroll
    for (int nt = 0; nt < NT; nt++) {
        int c = nt * 8 + t2;
        float d0 = acc[nt][0], d1 = acc[nt][1], d2 = acc[nt][2], d3 = acc[nt][3];
        if (EPI == 0) {
            if (r0 < n) {
                __half2 hh = __floats2half2_rn(d0, d1);
                *(uint32_t*)(outh + (size_t)r0 * FO + c) = *(uint32_t*)&hh;
            }
            if (r1 < n) {
                __half2 hh = __floats2half2_rn(d2, d3);
                *(uint32_t*)(outh + (size_t)r1 * FO + c) = *(uint32_t*)&hh;
            }
        } else if (EPI == 1 || EPI == 2) {
            float bc0 = __ldg(bepi + c), bc1 = __ldg(bepi + c + 1);
            if (r0 < n) {
                float v0 = fmaxf(fmaf(d0, dv0, bc0), 0.f);
                float v1 = fmaxf(fmaf(d1, dv0, bc1), 0.f);
                if (EPI == 1) { v0 *= dv0; v1 *= dv0; }
                __half2 hh = __floats2half2_rn(v0, v1);
                *(uint32_t*)(outh + (size_t)r0 * FO + c) = *(uint32_t*)&hh;
            }
            if (r1 < n) {
                float v0 = fmaxf(fmaf(d2, dv1, bc0), 0.f);
                float v1 = fmaxf(fmaf(d3, dv1, bc1), 0.f);
                if (EPI == 1) { v0 *= dv1; v1 *= dv1; }
                __half2 hh = __floats2half2_rn(v0, v1);
                *(uint32_t*)(outh + (size_t)r1 * FO + c) = *(uint32_t*)&hh;
            }
        } else {
            float add0 = __ldg(bepi + c), add1 = __ldg(bepi + c + 1);
            if (r0 < n) *(float2*)(outf + (size_t)r0 * FO + c) = make_float2(d0 + add0, d1 + add1);
            if (r1 < n) *(float2*)(outf + (size_t)r1 * FO + c) = make_float2(d2 + add0, d3 + add1);
        }
    }
}

// ---------------------------------------------------------------------------
// CSR gather-reduce (fp16 in, fp32 accumulate, fp16 out).
// s = src[i] + sum_{j in N(i)} src[j]
// GM 0: out = f16(s)
// GM 1: out = f16(dinv * relu(dinv * s + bias))
// Indices fetched 4-at-a-time (uniform int4 LDG per node-group).
// ---------------------------------------------------------------------------
template <int FO, int GM>
__global__ __launch_bounds__(256)
void k_gather(const __half* __restrict__ gsrc, __half* __restrict__ gdst,
              const float* __restrict__ bias, int n)
{
    constexpr int LPN = FO / 2;                // lanes per node (2 halves/lane)
    constexpr int NPW = 32 / LPN;              // nodes per warp

    int warp = (blockIdx.x * 256 + threadIdx.x) >> 5;
    int lane = threadIdx.x & 31;
    int node = warp * NPW + lane / LPN;
    if (node >= n) return;
    int li  = lane % LPN;
    int beg = g_offs[node];
    int end = g_offs[node + 1];

    const __half* base = gsrc + li * 2;

    float a0, a1;
    {
        uint32_t u = __ldg((const uint32_t*)(base + (size_t)node * FO));
        float2 f = __half22float2(*(__half2*)&u);
        a0 = f.x; a1 = f.y;
    }

    auto accum1 = [&](int s) {
        uint32_t u = __ldg((const uint32_t*)(base + (size_t)s * FO));
        float2 f = __half22float2(*(__half2*)&u);
        a0 += f.x; a1 += f.y;
    };

    int e = beg;
    while (e < end && (e & 3)) { accum1(__ldg(g_csr + e)); e++; }

    for (; e + 3 < end; e += 4) {
        int4 iv = __ldg((const int4*)(g_csr + e));   // uniform in node-group: 1 LDG
        uint32_t u0 = __ldg((const uint32_t*)(base + (size_t)iv.x * FO));
        uint32_t u1 = __ldg((const uint32_t*)(base + (size_t)iv.y * FO));
        uint32_t u2 = __ldg((const uint32_t*)(base + (size_t)iv.z * FO));
        uint32_t u3 = __ldg((const uint32_t*)(base + (size_t)iv.w * FO));
        float2 f0 = __half22float2(*(__half2*)&u0);
        float2 f1 = __half22float2(*(__half2*)&u1);
        float2 f2 = __half22float2(*(__half2*)&u2);
        float2 f3 = __half22float2(*(__half2*)&u3);
        a0 += (f0.x + f1.x) + (f2.x + f3.x);
        a1 += (f0.y + f1.y) + (f2.y + f3.y);
    }
    for (; e < end; e++) accum1(__ldg(g_csr + e));

    float v0, v1;
    if (GM == 0) {
        v0 = a0; v1 = a1;
    } else {
        float dv = g_dinv[node];
        v0 = dv * fmaxf(fmaf(a0, dv, __ldg(bias + li * 2 + 0)), 0.f);
        v1 = dv * fmaxf(fmaf(a1, dv, __ldg(bias + li * 2 + 1)), 0.f);
    }
    __half2 hh = __floats2half2_rn(v0, v1);
    *(uint32_t*)(gdst + (size_t)node * FO + li * 2) = *(uint32_t*)&hh;
}

// ---------------------------------------------------------------------------
// Host launcher
// ---------------------------------------------------------------------------
template <int FI, int FO, int PRO, int EPI>
static void launch_tgemm(const __half* inh, const float* inf, const float* W,
                         const float* bepi, __half* outh, float* outf, int n)
{
    constexpr int SM = (64 * (FI + 8) + FI * (FO + 8)) * 2;
    cudaFuncSetAttribute((const void*)k_tgemm<FI, FO, PRO, EPI>,
                         cudaFuncAttributeMaxDynamicSharedMemorySize, SM);
    k_tgemm<FI, FO, PRO, EPI><<<(n + 63) / 64, 128, SM>>>(inh, inf, W, bepi, outh, outf, n);
}

template <int FO, int GM>
static void launch_gather(const __half* src, __half* dst, const float* bias, int n)
{
    constexpr int NPW = 32 / (FO / 2);
    int warps  = (n + NPW - 1) / NPW;
    int blocks = (warps + 7) / 8;
    k_gather<FO, GM><<<blocks, 256>>>(src, dst, bias, n);
}

extern "C" void kernel_launch(void* const* d_in, const int* in_sizes, int n_in,
                              void* d_out, int out_size)
{
    const float* x  = (const float*)d_in[0];
    const int*   ei = (const int*)d_in[1];
    const int n = in_sizes[0] / 128;
    const int E = in_sizes[1] / 2;
    const int* row = ei;        // source j
    const int* col = ei + E;    // target i

    const float* W1 = (const float*)d_in[3];  const float* b1 = (const float*)d_in[4];
    const float* W2 = (const float*)d_in[5];  const float* b2 = (const float*)d_in[6];
    const float* W3 = (const float*)d_in[7];  const float* b3 = (const float*)d_in[8];
    const float* W4 = (const float*)d_in[9];  const float* b4 = (const float*)d_in[10];
    const float* W5 = (const float*)d_in[11]; const float* b5 = (const float*)d_in[12];
    const float* W6 = (const float*)d_in[13]; const float* b6 = (const float*)d_in[14];
    const float* Wf = (const float*)d_in[15]; const float* bf = (const float*)d_in[16];

    __half *A, *B;
    cudaGetSymbolAddress((void**)&A, g_bufA);
    cudaGetSymbolAddress((void**)&B, g_bufB);
    float* dout = (float*)d_out;

    // Degree + dinv + CSR (recomputed every replay: deterministic, capture-safe)
    k_zero<<<(n + 255) / 256, 256>>>(n);
    k_count<<<(E + 255) / 256, 256>>>(col, E);
    int nb = (n + 1023) / 1024;
    k_scan1<<<nb, 1024>>>(n);
    k_scan2<<<1, 128>>>(nb);
    k_scan3<<<(n + 255) / 256, 256>>>(n, E);
    k_fill<<<(E + 255) / 256, 256>>>(row, col, E);

    // L1 (TF, 128->64): t1 = (dinv*x)@W1 ; gather -> u2 = dinv*relu(dinv*S+b1)
    launch_tgemm<128, 64, 2, 0>(nullptr, x, W1, nullptr, A, nullptr, n);
    launch_gather<64, 1>(A, B, b1, n);

    // L2 (TF, 64->32): t2 = u2@W2 ; gather -> u3
    launch_tgemm<64, 32, 0, 0>(B, nullptr, W2, nullptr, A, nullptr, n);
    launch_gather<32, 1>(A, B, b2, n);

    // L3 (TF, 32->16): t3 = u3@W3 ; gather -> u4
    launch_tgemm<32, 16, 0, 0>(B, nullptr, W3, nullptr, A, nullptr, n);
    launch_gather<16, 1>(A, B, b3, n);

    // L4 (AF, 16->32): gather u4 -> U4 ; GEMM epi1(b4) -> u5
    launch_gather<16, 0>(B, A, nullptr, n);
    launch_tgemm<16, 32, 0, 1>(A, nullptr, W4, b4, B, nullptr, n);

    // L5 (AF, 32->64): gather u5 -> U5 ; GEMM epi1(b5) -> u6
    launch_gather<32, 0>(B, A, nullptr, n);
    launch_tgemm<32, 64, 0, 1>(A, nullptr, W5, b5, B, nullptr, n);

    // L6 (AF, 64->128): gather u6 -> U6 ; GEMM epi2(b6) -> a7 = relu(dinv*dot+b6)
    launch_gather<64, 0>(B, A, nullptr, n);
    launch_tgemm<64, 128, 0, 2>(A, nullptr, W6, b6, B, nullptr, n);

    // Final: out = a7@Wf + bf (fp32)
    launch_tgemm<128, 128, 0, 3>(B, nullptr, Wf, bf, nullptr, dout, n);
}

// round 11
// speedup vs baseline: 4.5343x; 1.0286x over previous
#include <cuda_runtime.h>
#include <cuda_fp16.h>
#include <cstdint>
#include <cstddef>

#define MAXN 100000
#define MAXE 3200000

// Scratch (device globals: allocation-free, rewritten every replay)
__device__ __half g_bufA[MAXN * 128];  // fp16 ping
__device__ __half g_bufB[MAXN * 128];  // fp16 pong
__device__ float  g_dinv[MAXN];
__device__ int    g_deg[MAXN];
__device__ int    g_offs[MAXN + 1];
__device__ int    g_cur[MAXN];
__device__ int    g_csr[MAXE];         // edge sources grouped by destination
__device__ int    g_part[128];

__device__ __forceinline__ uint32_t smem_u32(const void* p) {
    return (uint32_t)__cvta_generic_to_shared(p);
}

// ---------------------------------------------------------------------------
// Degree / dinv / CSR build  (deg zeroed by cudaMemsetAsync host-side)
// ---------------------------------------------------------------------------
__global__ void k_count(const int* __restrict__ col, int E) {
    int i = blockIdx.x * blockDim.x + threadIdx.x;
    if (i < E) atomicAdd(&g_deg[col[i]], 1);
}

__global__ __launch_bounds__(1024) void k_scan1(int n) {
    __shared__ int sh[1024];
    int i = blockIdx.x * 1024 + threadIdx.x;
    int v = (i < n) ? g_deg[i] : 0;
    sh[threadIdx.x] = v;
    __syncthreads();
    for (int d = 1; d < 1024; d <<= 1) {
        int t = (threadIdx.x >= d) ? sh[threadIdx.x - d] : 0;
        __syncthreads();
        sh[threadIdx.x] += t;
        __syncthreads();
    }
    if (i < n) g_offs[i] = sh[threadIdx.x] - v;  // exclusive within block
    if (threadIdx.x == 1023) g_part[blockIdx.x] = sh[1023];
}

// Merged: scan block partials (redundantly per block), add offset,
// cursor = start offset, dinv, sentinel.
__global__ __launch_bounds__(256) void k_finish(int n, int E, int nb) {
    __shared__ int sp[128];
    int tid = threadIdx.x;
    if (tid < 128) sp[tid] = (tid < nb) ? g_part[tid] : 0;
    __syncthreads();
    for (int d = 1; d < 128; d <<= 1) {
        int t = 0;
        if (tid < 128 && tid >= d) t = sp[tid - d];
        __syncthreads();
        if (tid < 128) sp[tid] += t;
        __syncthreads();
    }
    int i = blockIdx.x * 256 + tid;
    if (i < n) {
        int b = i >> 10;
        int off = (b == 0) ? 0 : sp[b - 1];
        int o = g_offs[i] + off;
        g_offs[i] = o;
        g_cur[i]  = o;  // fill cursor starts at segment base
        g_dinv[i] = rsqrtf((float)g_deg[i] + 1.0f);
    }
    if (i == 0) g_offs[n] = E;
}

__global__ void k_fill(const int* __restrict__ row, const int* __restrict__ col, int E) {
    int e = blockIdx.x * blockDim.x + threadIdx.x;
    if (e < E) {
        int p = atomicAdd(&g_cur[col[e]], 1);
        g_csr[p] = row[e];
    }
}

// ---------------------------------------------------------------------------
// Tensor-core GEMM (mma.sync m16n8k16, f16 x f16 -> f32).
// Block = 128 threads (4 warps), tile = 64 nodes x FO.
// PRO 0: A = fp16 input raw.     PRO 2: A = f16(dinv * fp32 input)   (L1)
// EPI 0: outh = f16(dot)
// EPI 1: outh = f16(dinv * relu(dinv * dot + bepi))
// EPI 2: outh = f16(relu(dinv * dot + bepi))
// EPI 3: outf = dot + bepi
// ---------------------------------------------------------------------------
template <int FI, int FO, int PRO, int EPI>
__global__ __launch_bounds__(128)
void k_tgemm(const __half* __restrict__ inh, const float* __restrict__ inf,
             const float* __restrict__ W, const float* __restrict__ bepi,
             __half* __restrict__ outh, float* __restrict__ outf, int n)
{
    constexpr int SA = FI + 8;
    constexpr int SW = FO + 8;
    extern __shared__ char smraw[];
    __half* sA = (__half*)smraw;            // 64 x SA
    __half* sW = (__half*)smraw + 64 * SA;  // FI x SW

    const int tid   = threadIdx.x;
    const int node0 = blockIdx.x * 64;

    if (PRO == 0) {
        for (int i = tid; i < 64 * (FI / 8); i += 128) {
            int node = i / (FI / 8);
            int f8   = i % (FI / 8);
            int gn   = node0 + node;
            uint4 v = make_uint4(0, 0, 0, 0);
            if (gn < n) v = *(const uint4*)(inh + (size_t)gn * FI + f8 * 8);
            *(uint4*)(sA + node * SA + f8 * 8) = v;
        }
    } else {
        for (int i = tid; i < 64 * (FI / 4); i += 128) {
            int node = i / (FI / 4);
            int fc   = i % (FI / 4);
            int f    = fc * 4;
            int gn   = node0 + node;
            float4 v = make_float4(0.f, 0.f, 0.f, 0.f);
            float dv = 0.f;
            if (gn < n) {
                v = *(const float4*)(inf + (size_t)gn * FI + f);
                dv = g_dinv[gn];
            }
            __half2 h01 = __floats2half2_rn(v.x * dv, v.y * dv);
            __half2 h23 = __floats2half2_rn(v.z * dv, v.w * dv);
            *(uint2*)(sA + node * SA + f) = make_uint2(*(uint32_t*)&h01, *(uint32_t*)&h23);
        }
    }
    for (int i = tid; i < FI * (FO / 4); i += 128) {
        int k  = i / (FO / 4);
        int nc = i % (FO / 4);
        int nn = nc * 4;
        float4 w = __ldg((const float4*)(W + (size_t)k * FO + nn));
        __half2 h01 = __floats2half2_rn(w.x, w.y);
        __half2 h23 = __floats2half2_rn(w.z, w.w);
        *(uint2*)(sW + k * SW + nn) = make_uint2(*(uint32_t*)&h01, *(uint32_t*)&h23);
    }
    __syncthreads();

    const int w    = tid >> 5;
    const int lane = tid & 31;
    constexpr int NT = FO / 8;

    float acc[NT][4];
    #pragma unroll
    for (int t = 0; t < NT; t++) {
        acc[t][0] = 0.f; acc[t][1] = 0.f; acc[t][2] = 0.f; acc[t][3] = 0.f;
    }

    const uint32_t aBase = smem_u32(sA);
    const uint32_t wBase = smem_u32(sW);
    const int arow = w * 16 + (lane & 15);
    const int asel = (lane >> 4) * 8;

    #pragma unroll
    for (int kk = 0; kk < FI / 16; kk++) {
        uint32_t a0, a1, a2, a3;
        {
            uint32_t addrA = aBase + (uint32_t)((arow * SA + kk * 16 + asel) * 2);
            asm volatile("ldmatrix.sync.aligned.m8n8.x4.shared.b16 {%0,%1,%2,%3}, [%4];"
                         : "=r"(a0), "=r"(a1), "=r"(a2), "=r"(a3) : "r"(addrA));
        }
        const int krow = kk * 16 + (lane & 15);
        #pragma unroll
        for (int nt = 0; nt < NT; nt++) {
            uint32_t b0, b1;
            uint32_t addrB = wBase + (uint32_t)((krow * SW + nt * 8) * 2);
            asm volatile("ldmatrix.sync.aligned.m8n8.x2.trans.shared.b16 {%0,%1}, [%2];"
                         : "=r"(b0), "=r"(b1) : "r"(addrB));
            asm volatile("mma.sync.aligned.m16n8k16.row.col.f32.f16.f16.f32 "
                         "{%0,%1,%2,%3}, {%4,%5,%6,%7}, {%8,%9}, {%0,%1,%2,%3};"
                         : "+f"(acc[nt][0]), "+f"(acc[nt][1]),
                           "+f"(acc[nt][2]), "+f"(acc[nt][3])
                         : "r"(a0), "r"(a1), "r"(a2), "r"(a3), "r"(b0), "r"(b1));
        }
    }

    const int g8 = lane >> 2;
    const int t2 = (lane & 3) * 2;
    const int r0 = node0 + w * 16 + g8;
    const int r1 = r0 + 8;
    float dv0 = 0.f, dv1 = 0.f;
    if (EPI == 1 || EPI == 2) {
        if (r0 < n) dv0 = g_dinv[r0];
        if (r1 < n) dv1 = g_dinv[r1];
    }
    #pragma unroll
    for (int nt = 0; nt < NT; nt++) {
        int c = nt * 8 + t2;
        float d0 = acc[nt][0], d1 = acc[nt][1], d2 = acc[nt][2], d3 = acc[nt][3];
        if (EPI == 0) {
            if (r0 < n) {
                __half2 hh = __floats2half2_rn(d0, d1);
                *(uint32_t*)(outh + (size_t)r0 * FO + c) = *(uint32_t*)&hh;
            }
            if (r1 < n) {
                __half2 hh = __floats2half2_rn(d2, d3);
                *(uint32_t*)(outh + (size_t)r1 * FO + c) = *(uint32_t*)&hh;
            }
        } else if (EPI == 1 || EPI == 2) {
            float bc0 = __ldg(bepi + c), bc1 = __ldg(bepi + c + 1);
            if (r0 < n) {
                float v0 = fmaxf(fmaf(d0, dv0, bc0), 0.f);
                float v1 = fmaxf(fmaf(d1, dv0, bc1), 0.f);
                if (EPI == 1) { v0 *= dv0; v1 *= dv0; }
                __half2 hh = __floats2half2_rn(v0, v1);
                *(uint32_t*)(outh + (size_t)r0 * FO + c) = *(uint32_t*)&hh;
            }
            if (r1 < n) {
                float v0 = fmaxf(fmaf(d2, dv1, bc0), 0.f);
                float v1 = fmaxf(fmaf(d3, dv1, bc1), 0.f);
                if (EPI == 1) { v0 *= dv1; v1 *= dv1; }
                __half2 hh = __floats2half2_rn(v0, v1);
                *(uint32_t*)(outh + (size_t)r1 * FO + c) = *(uint32_t*)&hh;
            }
        } else {
            float add0 = __ldg(bepi + c), add1 = __ldg(bepi + c + 1);
            if (r0 < n) *(float2*)(outf + (size_t)r0 * FO + c) = make_float2(d0 + add0, d1 + add1);
            if (r1 < n) *(float2*)(outf + (size_t)r1 * FO + c) = make_float2(d2 + add0, d3 + add1);
        }
    }
}

// ---------------------------------------------------------------------------
// CSR gather-reduce (fp16 in, fp32 accumulate, fp16 out).
// 8-byte lane loads (HPL=4), 8-edge unroll -> MLP=8 per lane.
// GM 0: out = f16(s)          GM 1: out = f16(dinv * relu(dinv * s + bias))
// ---------------------------------------------------------------------------
template <int FO, int GM>
__global__ __launch_bounds__(256)
void k_gather(const __half* __restrict__ gsrc, __half* __restrict__ gdst,
              const float* __restrict__ bias, int n)
{
    constexpr int HPL = 4;                 // halves per lane (8B loads)
    constexpr int LPN = FO / HPL;          // lanes per node
    constexpr int NPW = 32 / LPN;          // nodes per warp

    int warp = (blockIdx.x * 256 + threadIdx.x) >> 5;
    int lane = threadIdx.x & 31;
    int node = warp * NPW + lane / LPN;
    if (node >= n) return;
    int li  = lane % LPN;
    int beg = g_offs[node];
    int end = g_offs[node + 1];

    const __half* base = gsrc + li * HPL;

    float a0, a1, a2, a3;
    {
        uint2 u = __ldg((const uint2*)(base + (size_t)node * FO));
        float2 f0 = __half22float2(*(__half2*)&u.x);
        float2 f1 = __half22float2(*(__half2*)&u.y);
        a0 = f0.x; a1 = f0.y; a2 = f1.x; a3 = f1.y;
    }

    auto addrow = [&](int s) {
        uint2 u = __ldg((const uint2*)(base + (size_t)s * FO));
        float2 f0 = __half22float2(*(__half2*)&u.x);
        float2 f1 = __half22float2(*(__half2*)&u.y);
        a0 += f0.x; a1 += f0.y; a2 += f1.x; a3 += f1.y;
    };

    int e = beg;
    while (e < end && (e & 3)) { addrow(__ldg(g_csr + e)); e++; }

    for (; e + 7 < end; e += 8) {
        int4 iv0 = __ldg((const int4*)(g_csr + e));
        int4 iv1 = __ldg((const int4*)(g_csr + e + 4));
        int idx[8] = {iv0.x, iv0.y, iv0.z, iv0.w, iv1.x, iv1.y, iv1.z, iv1.w};
        uint2 us[8];
        #pragma unroll
        for (int q = 0; q < 8; q++)
            us[q] = __ldg((const uint2*)(base + (size_t)idx[q] * FO));
        float x0[8], x1[8], x2[8], x3[8];
        #pragma unroll
        for (int q = 0; q < 8; q++) {
            float2 f0 = __half22float2(*(__half2*)&us[q].x);
            float2 f1 = __half22float2(*(__half2*)&us[q].y);
            x0[q] = f0.x; x1[q] = f0.y; x2[q] = f1.x; x3[q] = f1.y;
        }
        a0 += ((x0[0] + x0[1]) + (x0[2] + x0[3])) + ((x0[4] + x0[5]) + (x0[6] + x0[7]));
        a1 += ((x1[0] + x1[1]) + (x1[2] + x1[3])) + ((x1[4] + x1[5]) + (x1[6] + x1[7]));
        a2 += ((x2[0] + x2[1]) + (x2[2] + x2[3])) + ((x2[4] + x2[5]) + (x2[6] + x2[7]));
        a3 += ((x3[0] + x3[1]) + (x3[2] + x3[3])) + ((x3[4] + x3[5]) + (x3[6] + x3[7]));
    }
    for (; e + 3 < end; e += 4) {
        int4 iv = __ldg((const int4*)(g_csr + e));
        uint2 u0 = __ldg((const uint2*)(base + (size_t)iv.x * FO));
        uint2 u1 = __ldg((const uint2*)(base + (size_t)iv.y * FO));
        uint2 u2 = __ldg((const uint2*)(base + (size_t)iv.z * FO));
        uint2 u3 = __ldg((const uint2*)(base + (size_t)iv.w * FO));
        float2 f0a = __half22float2(*(__half2*)&u0.x), f0b = __half22float2(*(__half2*)&u0.y);
        float2 f1a = __half22float2(*(__half2*)&u1.x), f1b = __half22float2(*(__half2*)&u1.y);
        float2 f2a = __half22float2(*(__half2*)&u2.x), f2b = __half22float2(*(__half2*)&u2.y);
        float2 f3a = __half22float2(*(__half2*)&u3.x), f3b = __half22float2(*(__half2*)&u3.y);
        a0 += (f0a.x + f1a.x) + (f2a.x + f3a.x);
        a1 += (f0a.y + f1a.y) + (f2a.y + f3a.y);
        a2 += (f0b.x + f1b.x) + (f2b.x + f3b.x);
        a3 += (f0b.y + f1b.y) + (f2b.y + f3b.y);
    }
    for (; e < end; e++) addrow(__ldg(g_csr + e));

    float v0, v1, v2, v3;
    if (GM == 0) {
        v0 = a0; v1 = a1; v2 = a2; v3 = a3;
    } else {
        float dv = g_dinv[node];
        v0 = dv * fmaxf(fmaf(a0, dv, __ldg(bias + li * HPL + 0)), 0.f);
        v1 = dv * fmaxf(fmaf(a1, dv, __ldg(bias + li * HPL + 1)), 0.f);
        v2 = dv * fmaxf(fmaf(a2, dv, __ldg(bias + li * HPL + 2)), 0.f);
        v3 = dv * fmaxf(fmaf(a3, dv, __ldg(bias + li * HPL + 3)), 0.f);
    }
    __half2 h01 = __floats2half2_rn(v0, v1);
    __half2 h23 = __floats2half2_rn(v2, v3);
    *(uint2*)(gdst + (size_t)node * FO + li * HPL) =
        make_uint2(*(uint32_t*)&h01, *(uint32_t*)&h23);
}

// ---------------------------------------------------------------------------
// Host launcher
// ---------------------------------------------------------------------------
template <int FI, int FO, int PRO, int EPI>
static void launch_tgemm(const __half* inh, const float* inf, const float* W,
                         const float* bepi, __half* outh, float* outf, int n)
{
    constexpr int SM = (64 * (FI + 8) + FI * (FO + 8)) * 2;
    cudaFuncSetAttribute((const void*)k_tgemm<FI, FO, PRO, EPI>,
                         cudaFuncAttributeMaxDynamicSharedMemorySize, SM);
    k_tgemm<FI, FO, PRO, EPI><<<(n + 63) / 64, 128, SM>>>(inh, inf, W, bepi, outh, outf, n);
}

template <int FO, int GM>
static void launch_gather(const __half* src, __half* dst, const float* bias, int n)
{
    constexpr int NPW = 32 / (FO / 4);
    int warps  = (n + NPW - 1) / NPW;
    int blocks = (warps + 7) / 8;
    k_gather<FO, GM><<<blocks, 256>>>(src, dst, bias, n);
}

extern "C" void kernel_launch(void* const* d_in, const int* in_sizes, int n_in,
                              void* d_out, int out_size)
{
    const float* x  = (const float*)d_in[0];
    const int*   ei = (const int*)d_in[1];
    const int n = in_sizes[0] / 128;
    const int E = in_sizes[1] / 2;
    const int* row = ei;        // source j
    const int* col = ei + E;    // target i

    const float* W1 = (const float*)d_in[3];  const float* b1 = (const float*)d_in[4];
    const float* W2 = (const float*)d_in[5];  const float* b2 = (const float*)d_in[6];
    const float* W3 = (const float*)d_in[7];  const float* b3 = (const float*)d_in[8];
    const float* W4 = (const float*)d_in[9];  const float* b4 = (const float*)d_in[10];
    const float* W5 = (const float*)d_in[11]; const float* b5 = (const float*)d_in[12];
    const float* W6 = (const float*)d_in[13]; const float* b6 = (const float*)d_in[14];
    const float* Wf = (const float*)d_in[15]; const float* bf = (const float*)d_in[16];

    __half *A, *B; int* degPtr;
    cudaGetSymbolAddress((void**)&A, g_bufA);
    cudaGetSymbolAddress((void**)&B, g_bufB);
    cudaGetSymbolAddress((void**)&degPtr, g_deg);
    float* dout = (float*)d_out;

    // Degree + dinv + CSR (recomputed every replay: deterministic, capture-safe)
    cudaMemsetAsync(degPtr, 0, (size_t)n * sizeof(int));
    k_count<<<(E + 255) / 256, 256>>>(col, E);
    int nb = (n + 1023) / 1024;
    k_scan1<<<nb, 1024>>>(n);
    k_finish<<<(n + 255) / 256, 256>>>(n, E, nb);
    k_fill<<<(E + 255) / 256, 256>>>(row, col, E);

    // L1 (TF, 128->64): t1 = (dinv*x)@W1 ; gather -> u2 = dinv*relu(dinv*S+b1)
    launch_tgemm<128, 64, 2, 0>(nullptr, x, W1, nullptr, A, nullptr, n);
    launch_gather<64, 1>(A, B, b1, n);

    // L2 (TF, 64->32): t2 = u2@W2 ; gather -> u3
    launch_tgemm<64, 32, 0, 0>(B, nullptr, W2, nullptr, A, nullptr, n);
    launch_gather<32, 1>(A, B, b2, n);

    // L3 (TF, 32->16): t3 = u3@W3 ; gather -> u4
    launch_tgemm<32, 16, 0, 0>(B, nullptr, W3, nullptr, A, nullptr, n);
    launch_gather<16, 1>(A, B, b3, n);

    // L4 (AF, 16->32): gather u4 -> U4 ; GEMM epi1(b4) -> u5
    launch_gather<16, 0>(B, A, nullptr, n);
    launch_tgemm<16, 32, 0, 1>(A, nullptr, W4, b4, B, nullptr, n);

    // L5 (AF, 32->64): gather u5 -> U5 ; GEMM epi1(b5) -> u6
    launch_gather<32, 0>(B, A, nullptr, n);
    launch_tgemm<32, 64, 0, 1>(A, nullptr, W5, b5, B, nullptr, n);

    // L6 (AF, 64->128): gather u6 -> U6 ; GEMM epi2(b6) -> a7 = relu(dinv*dot+b6)
    launch_gather<64, 0>(B, A, nullptr, n);
    launch_tgemm<64, 128, 0, 2>(A, nullptr, W6, b6, B, nullptr, n);

    // Final: out = a7@Wf + bf (fp32)
    launch_tgemm<128, 128, 0, 3>(B, nullptr, Wf, bf, nullptr, dout, n);
}